// round 5
// baseline (speedup 1.0000x reference)
#include <cuda_runtime.h>
#include <math.h>

#define NMAX 100000
#define EMAX 2000000
#define DIM 128
#define LN_EPS 1e-5f

typedef unsigned long long u64;

// ---------------- packed f32x2 helpers (sm_103a) ----------------
#define FMA_F32X2(d, a, b) \
    asm("fma.rn.f32x2 %0, %1, %2, %0;" : "+l"(d) : "l"(a), "l"(b))
#define PACK_F32X2(out, lo, hi) \
    asm("mov.b64 %0, {%1, %2};" : "=l"(out) : "f"(lo), "f"(hi))
#define UNPACK_F32X2(lo, hi, in) \
    asm("mov.b64 {%0, %1}, %2;" : "=f"(lo), "=f"(hi) : "l"(in))

// ---------------- static scratch ----------------
__device__ int   g_deg [NMAX];
__device__ int   g_off [NMAX + 1];
__device__ int   g_cur [NMAX];
__device__ int   g_srcs[EMAX];
__device__ float g_dinv[NMAX];
__device__ float g_bufA[(size_t)NMAX * DIM];   // z = (h @ W) * dinv[row]
__device__ float g_bufC[(size_t)NMAX * DIM];   // layer activations

// ---------------- CSR build ----------------
__global__ void zero_deg_kernel(int* __restrict__ deg, int n) {
    int i = blockIdx.x * blockDim.x + threadIdx.x;
    if (i < n) deg[i] = 0;
}

__global__ void hist_kernel(const int* __restrict__ dst, int* __restrict__ deg, int E) {
    int e = blockIdx.x * blockDim.x + threadIdx.x;
    if (e < E) atomicAdd(&deg[dst[e]], 1);
}

// single block, 1024 threads: exclusive scan of deg -> off/cur, also dinv = rsqrt(deg+1)
__global__ __launch_bounds__(1024)
void scan_kernel(const int* __restrict__ deg, int* __restrict__ off, int* __restrict__ cur,
                 float* __restrict__ dinv, int n) {
    __shared__ int part[1024];
    const int tid = threadIdx.x;
    const int per = (n + 1023) / 1024;
    const int base = tid * per;
    int s = 0;
    for (int i = 0; i < per; i++) {
        int idx = base + i;
        if (idx < n) s += deg[idx];
    }
    part[tid] = s;
    __syncthreads();
    for (int o = 1; o < 1024; o <<= 1) {
        int v = (tid >= o) ? part[tid - o] : 0;
        __syncthreads();
        part[tid] += v;
        __syncthreads();
    }
    int run = (tid == 0) ? 0 : part[tid - 1];
    for (int i = 0; i < per; i++) {
        int idx = base + i;
        if (idx < n) {
            off[idx] = run;
            cur[idx] = run;
            dinv[idx] = rsqrtf((float)deg[idx] + 1.0f);
            run += deg[idx];
            if (idx == n - 1) off[n] = run;
        }
    }
}

__global__ void bucket_kernel(const int* __restrict__ src, const int* __restrict__ dst,
                              int* __restrict__ cur, int* __restrict__ sorted, int E) {
    int e = blockIdx.x * blockDim.x + threadIdx.x;
    if (e < E) {
        int p = atomicAdd(&cur[dst[e]], 1);
        sorted[p] = src[e];
    }
}

// ---------------- persistent GEMM: out = A[M,128] @ W[128,BN] ----------------
// 148 blocks x 256 threads; W staged once; BM=128 row tiles.
// Thread (tr=tid>>4, cx=tid&15): 8 rows (r0=8*tr) x 8 cols ({g*64 + 4*cx..+3}).
// Per k per thread: 2 LDS.128 A (broadcast) + 2x16B W (conflict-free) -> 32 FFMA2.
// MODE 0: v *= dinv[row]    MODE 1: v += bias    MODE 2: v = sigmoid(v + bias)
template <int BN, int MODE>
__global__ __launch_bounds__(256)
void gemm_kernel(const float* __restrict__ A, const float* __restrict__ W,
                 const float* __restrict__ bias, const float* __restrict__ dinv,
                 float* __restrict__ out1, int M, int ntiles) {
    constexpr int BM = 128;
    constexpr int NG = BN / 64;           // 64-col groups (2 or 1)
    constexpr int SAS = BM + 4;           // 132: multiple of 4 -> 16B-aligned float4 rows

    extern __shared__ float smem[];
    float* sW  = smem;                    // [128][BN]
    float* sAT = smem + 128 * BN;         // [128][SAS]  A transposed: sAT[k][m]

    const int tid = threadIdx.x;
    const int cx = tid & 15;
    const int tr = tid >> 4;
    const int r0 = tr * 8;

    // stage W once
    {
        const float4* Wv = (const float4*)W;
        float4* sWv = (float4*)sW;
        for (int i = tid; i < 128 * BN / 4; i += 256) sWv[i] = Wv[i];
    }

    float bv[NG][4];
    if (MODE != 0) {
#pragma unroll
        for (int g = 0; g < NG; g++)
#pragma unroll
            for (int j = 0; j < 4; j++) bv[g][j] = __ldg(&bias[g * 64 + cx * 4 + j]);
    }

    for (int tile = blockIdx.x; tile < ntiles; tile += gridDim.x) {
        const int rowbase = tile * BM;
        const int nrows = min(BM, M - rowbase);

        __syncthreads();   // previous iteration's readers done
        // load A tile (128 x 128) transposed into sAT[k][m]
        for (int i = tid; i < BM * 32; i += 256) {
            int r = i >> 5, c4 = i & 31;
            float4 v = make_float4(0.f, 0.f, 0.f, 0.f);
            if (r < nrows)
                v = ((const float4*)(A + (size_t)(rowbase + r) * 128))[c4];
            sAT[(4 * c4 + 0) * SAS + r] = v.x;
            sAT[(4 * c4 + 1) * SAS + r] = v.y;
            sAT[(4 * c4 + 2) * SAS + r] = v.z;
            sAT[(4 * c4 + 3) * SAS + r] = v.w;
        }
        __syncthreads();

        u64 acc[8][NG][2];
#pragma unroll
        for (int i = 0; i < 8; i++)
#pragma unroll
            for (int g = 0; g < NG; g++) { acc[i][g][0] = 0ULL; acc[i][g][1] = 0ULL; }

#pragma unroll 4
        for (int k = 0; k < 128; k++) {
            const float* arow = &sAT[k * SAS + r0];
            float4 a0 = *(const float4*)(arow);         // rows r0..r0+3
            float4 a1 = *(const float4*)(arow + 4);     // rows r0+4..r0+7
            u64 aa[8];
            PACK_F32X2(aa[0], a0.x, a0.x);
            PACK_F32X2(aa[1], a0.y, a0.y);
            PACK_F32X2(aa[2], a0.z, a0.z);
            PACK_F32X2(aa[3], a0.w, a0.w);
            PACK_F32X2(aa[4], a1.x, a1.x);
            PACK_F32X2(aa[5], a1.y, a1.y);
            PACK_F32X2(aa[6], a1.z, a1.z);
            PACK_F32X2(aa[7], a1.w, a1.w);
#pragma unroll
            for (int g = 0; g < NG; g++) {
                const u64* w2 = (const u64*)&sW[k * BN + g * 64 + cx * 4];
                u64 w0 = w2[0], w1 = w2[1];
#pragma unroll
                for (int i = 0; i < 8; i++) {
                    FMA_F32X2(acc[i][g][0], aa[i], w0);
                    FMA_F32X2(acc[i][g][1], aa[i], w1);
                }
            }
        }

#pragma unroll
        for (int i = 0; i < 8; i++) {
            const int grow = rowbase + r0 + i;
            if (grow >= M) break;
            const float s = (MODE == 0) ? dinv[grow] : 0.f;
#pragma unroll
            for (int g = 0; g < NG; g++) {
                float v0, v1, v2, v3;
                UNPACK_F32X2(v0, v1, acc[i][g][0]);
                UNPACK_F32X2(v2, v3, acc[i][g][1]);
                float4* o = (float4*)(out1 + (size_t)grow * BN + g * 64 + cx * 4);
                if (MODE == 0) {
                    *o = make_float4(v0 * s, v1 * s, v2 * s, v3 * s);
                } else if (MODE == 1) {
                    *o = make_float4(v0 + bv[g][0], v1 + bv[g][1], v2 + bv[g][2], v3 + bv[g][3]);
                } else {
                    float t0 = v0 + bv[g][0], t1 = v1 + bv[g][1];
                    float t2 = v2 + bv[g][2], t3 = v3 + bv[g][3];
                    *o = make_float4(1.f / (1.f + expf(-t0)), 1.f / (1.f + expf(-t1)),
                                     1.f / (1.f + expf(-t2)), 1.f / (1.f + expf(-t3)));
                }
            }
        }
    }
}

// ---------------- fused CSR aggregate + self-loop + dinv + bias + ReLU (+LN) ----------------
// one warp per node; lane owns float4 (4 of 128 features)
template <int DO_LN>
__global__ __launch_bounds__(256)
void aggregate_kernel(const float4* __restrict__ z, const int* __restrict__ off,
                      const int* __restrict__ srcs, const float* __restrict__ dinv,
                      const float* __restrict__ b, const float* __restrict__ g,
                      const float* __restrict__ be, float4* __restrict__ out, int n) {
    const int warp = (blockIdx.x * blockDim.x + threadIdx.x) >> 5;
    const int lane = threadIdx.x & 31;
    if (warp >= n) return;

    const int s0 = __ldg(&off[warp]);
    const int s1 = __ldg(&off[warp + 1]);

    float4 acc = __ldg(&z[(size_t)warp * 32 + lane]);   // self loop (z already carries dinv[src])
    for (int base = s0; base < s1; base += 32) {
        const int cnt = min(32, s1 - base);
        int mys = (base + lane < s1) ? __ldg(&srcs[base + lane]) : 0;
#pragma unroll 8
        for (int j = 0; j < cnt; j++) {
            int sn = __shfl_sync(0xffffffffu, mys, j);
            float4 v = __ldg(&z[(size_t)sn * 32 + lane]);
            acc.x += v.x; acc.y += v.y; acc.z += v.z; acc.w += v.w;
        }
    }

    const float dv = __ldg(&dinv[warp]);
    const float4 bb = ((const float4*)b)[lane];
    float4 v = make_float4(fmaxf(fmaf(dv, acc.x, bb.x), 0.f),
                           fmaxf(fmaf(dv, acc.y, bb.y), 0.f),
                           fmaxf(fmaf(dv, acc.z, bb.z), 0.f),
                           fmaxf(fmaf(dv, acc.w, bb.w), 0.f));
    if (DO_LN) {
        float s = v.x + v.y + v.z + v.w;
#pragma unroll
        for (int o = 16; o > 0; o >>= 1) s += __shfl_xor_sync(0xffffffffu, s, o);
        const float mu = s * (1.f / 128.f);
        float4 xc = make_float4(v.x - mu, v.y - mu, v.z - mu, v.w - mu);
        float s2 = xc.x * xc.x + xc.y * xc.y + xc.z * xc.z + xc.w * xc.w;
#pragma unroll
        for (int o = 16; o > 0; o >>= 1) s2 += __shfl_xor_sync(0xffffffffu, s2, o);
        const float rs = rsqrtf(s2 * (1.f / 128.f) + LN_EPS);
        const float4 gg = ((const float4*)g)[lane];
        const float4 ee = ((const float4*)be)[lane];
        v = make_float4(fmaf(gg.x * xc.x, rs, ee.x), fmaf(gg.y * xc.y, rs, ee.y),
                        fmaf(gg.z * xc.z, rs, ee.z), fmaf(gg.w * xc.w, rs, ee.w));
    }
    out[(size_t)warp * 32 + lane] = v;
}

// ---------------- launch ----------------
extern "C" void kernel_launch(void* const* d_in, const int* in_sizes, int n_in,
                              void* d_out, int out_size) {
    const float* x   = (const float*)d_in[0];
    const int*   ei  = (const int*)  d_in[1];
    const float* W1  = (const float*)d_in[2];
    const float* b1  = (const float*)d_in[3];
    const float* W2  = (const float*)d_in[4];
    const float* b2  = (const float*)d_in[5];
    const float* W3  = (const float*)d_in[6];
    const float* b3  = (const float*)d_in[7];
    const float* g1  = (const float*)d_in[8];
    const float* be1 = (const float*)d_in[9];
    const float* g2  = (const float*)d_in[10];
    const float* be2 = (const float*)d_in[11];
    const float* Wp1 = (const float*)d_in[12];
    const float* bp1 = (const float*)d_in[13];
    const float* Wp2 = (const float*)d_in[14];
    const float* bp2 = (const float*)d_in[15];
    float* out = (float*)d_out;

    const int n = in_sizes[0] / DIM;          // 100000
    const int E = in_sizes[1] / 2;            // 1600000
    const int* src = ei;
    const int* dst = ei + E;

    int *deg, *off, *cur, *srcs;
    float *dinv, *bufA, *bufC;
    cudaGetSymbolAddress((void**)&deg,  g_deg);
    cudaGetSymbolAddress((void**)&off,  g_off);
    cudaGetSymbolAddress((void**)&cur,  g_cur);
    cudaGetSymbolAddress((void**)&srcs, g_srcs);
    cudaGetSymbolAddress((void**)&dinv, g_dinv);
    cudaGetSymbolAddress((void**)&bufA, g_bufA);
    cudaGetSymbolAddress((void**)&bufC, g_bufC);

    const int SMEM128 = (128 * 128 + 128 * 132) * 4;  // 133120 B
    const int SMEM64  = (128 * 64  + 128 * 132) * 4;  // 100352 B
    cudaFuncSetAttribute(gemm_kernel<128, 0>, cudaFuncAttributeMaxDynamicSharedMemorySize, SMEM128);
    cudaFuncSetAttribute(gemm_kernel<128, 1>, cudaFuncAttributeMaxDynamicSharedMemorySize, SMEM128);
    cudaFuncSetAttribute(gemm_kernel<64,  2>, cudaFuncAttributeMaxDynamicSharedMemorySize, SMEM64);

    const int ntiles = (n + 127) / 128;              // 782
    const int GEMM_GRID = 148;                       // persistent, 1 block/SM
    const int agg_grid = (n * 32 + 255) / 256;       // 1 warp per node

    // ---- CSR build (reused by all 3 convs) ----
    zero_deg_kernel<<<(n + 255) / 256, 256>>>(deg, n);
    hist_kernel<<<(E + 255) / 256, 256>>>(dst, deg, E);
    scan_kernel<<<1, 1024>>>(deg, off, cur, dinv, n);
    bucket_kernel<<<(E + 255) / 256, 256>>>(src, dst, cur, srcs, E);

    // ---- conv1 ----
    gemm_kernel<128, 0><<<GEMM_GRID, 256, SMEM128>>>(x, W1, nullptr, dinv, bufA, n, ntiles);
    aggregate_kernel<1><<<agg_grid, 256>>>((const float4*)bufA, off, srcs, dinv, b1, g1, be1, (float4*)bufC, n);

    // ---- conv2 ----
    gemm_kernel<128, 0><<<GEMM_GRID, 256, SMEM128>>>(bufC, W2, nullptr, dinv, bufA, n, ntiles);
    aggregate_kernel<1><<<agg_grid, 256>>>((const float4*)bufA, off, srcs, dinv, b2, g2, be2, (float4*)bufC, n);

    // ---- conv3 (no LN) ----
    gemm_kernel<128, 0><<<GEMM_GRID, 256, SMEM128>>>(bufC, W3, nullptr, dinv, bufA, n, ntiles);
    aggregate_kernel<0><<<agg_grid, 256>>>((const float4*)bufA, off, srcs, dinv, b3, nullptr, nullptr, (float4*)bufC, n);

    // ---- heads ----
    gemm_kernel<128, 1><<<GEMM_GRID, 256, SMEM128>>>(bufC, Wp1, bp1, nullptr, bufA, n, ntiles);
    gemm_kernel<64,  2><<<GEMM_GRID, 256, SMEM64 >>>(bufA, Wp2, bp2, nullptr, out,  n, ntiles);
}

// round 6
// speedup vs baseline: 1.1971x; 1.1971x over previous
#include <cuda_runtime.h>
#include <math.h>

#define NMAX 100000
#define EMAX 2000000
#define DIM 128
#define LN_EPS 1e-5f

typedef unsigned long long u64;

// ---------------- packed f32x2 helpers (sm_103a) ----------------
#define FMA_F32X2(d, a, b) \
    asm("fma.rn.f32x2 %0, %1, %2, %0;" : "+l"(d) : "l"(a), "l"(b))
#define PACK_F32X2(out, lo, hi) \
    asm("mov.b64 %0, {%1, %2};" : "=l"(out) : "f"(lo), "f"(hi))
#define UNPACK_F32X2(lo, hi, in) \
    asm("mov.b64 {%0, %1}, %2;" : "=f"(lo), "=f"(hi) : "l"(in))

// ---------------- static scratch ----------------
__device__ int   g_deg [NMAX];
__device__ int   g_off [NMAX + 1];
__device__ int   g_cur [NMAX];
__device__ int   g_srcs[EMAX];
__device__ float g_dinv[NMAX];
__device__ float g_Wf  [DIM * 64];     // fused head weight Wp1@Wp2
__device__ float g_bf  [64];           // fused head bias   bp1@Wp2 + bp2
__device__ float g_bufA[(size_t)NMAX * DIM];   // z = (h @ W) * dinv[row]
__device__ float g_bufC[(size_t)NMAX * DIM];   // layer activations

// ---------------- CSR build ----------------
__global__ void zero_deg_kernel(int* __restrict__ deg, int n) {
    int i = blockIdx.x * blockDim.x + threadIdx.x;
    if (i < n) deg[i] = 0;
}

__global__ void hist_kernel(const int* __restrict__ dst, int* __restrict__ deg, int E) {
    int e = blockIdx.x * blockDim.x + threadIdx.x;
    if (e < E) atomicAdd(&deg[dst[e]], 1);
}

// single block, 1024 threads: exclusive scan of deg -> off/cur, also dinv = rsqrt(deg+1)
__global__ __launch_bounds__(1024)
void scan_kernel(const int* __restrict__ deg, int* __restrict__ off, int* __restrict__ cur,
                 float* __restrict__ dinv, int n) {
    __shared__ int part[1024];
    const int tid = threadIdx.x;
    const int per = (n + 1023) / 1024;
    const int base = tid * per;
    int s = 0;
    for (int i = 0; i < per; i++) {
        int idx = base + i;
        if (idx < n) s += deg[idx];
    }
    part[tid] = s;
    __syncthreads();
    for (int o = 1; o < 1024; o <<= 1) {
        int v = (tid >= o) ? part[tid - o] : 0;
        __syncthreads();
        part[tid] += v;
        __syncthreads();
    }
    int run = (tid == 0) ? 0 : part[tid - 1];
    for (int i = 0; i < per; i++) {
        int idx = base + i;
        if (idx < n) {
            off[idx] = run;
            cur[idx] = run;
            dinv[idx] = rsqrtf((float)deg[idx] + 1.0f);
            run += deg[idx];
            if (idx == n - 1) off[n] = run;
        }
    }
}

__global__ void bucket_kernel(const int* __restrict__ src, const int* __restrict__ dst,
                              int* __restrict__ cur, int* __restrict__ sorted, int E) {
    int e = blockIdx.x * blockDim.x + threadIdx.x;
    if (e < E) {
        int p = atomicAdd(&cur[dst[e]], 1);
        sorted[p] = src[e];
    }
}

// ---------------- fuse heads: Wf = Wp1 @ Wp2, bf = bp1 @ Wp2 + bp2 ----------------
// 8192 + 64 outputs, each a 128-dot. 33 blocks x 256 threads.
__global__ void fuse_heads_kernel(const float* __restrict__ Wp1, const float* __restrict__ bp1,
                                  const float* __restrict__ Wp2, const float* __restrict__ bp2,
                                  float* __restrict__ Wf, float* __restrict__ bf) {
    int idx = blockIdx.x * blockDim.x + threadIdx.x;
    if (idx < 128 * 64) {
        int i = idx >> 6, j = idx & 63;
        float s = 0.f;
#pragma unroll 8
        for (int k = 0; k < 128; k++)
            s = fmaf(__ldg(&Wp1[i * 128 + k]), __ldg(&Wp2[k * 64 + j]), s);
        Wf[idx] = s;
    } else if (idx < 128 * 64 + 64) {
        int j = idx - 128 * 64;
        float s = __ldg(&bp2[j]);
#pragma unroll 8
        for (int k = 0; k < 128; k++)
            s = fmaf(__ldg(&bp1[k]), __ldg(&Wp2[k * 64 + j]), s);
        bf[j] = s;
    }
}

// ---------------- persistent GEMM: out = A[M,128] @ W[128,BN] ----------------
// 296 blocks x 256 threads (2/SM); W staged once; BM=64 row tiles.
// Thread (tr=tid>>4, cx=tid&15): 4 rows (r0=4*tr) x 8 cols ({g*64 + 4*cx..+3}).
// MODE 0: v *= dinv[row]    MODE 1: v += bias    MODE 2: v = sigmoid(v + bias)
template <int BN, int MODE>
__global__ __launch_bounds__(256)
void gemm_kernel(const float* __restrict__ A, const float* __restrict__ W,
                 const float* __restrict__ bias, const float* __restrict__ dinv,
                 float* __restrict__ out1, int M, int ntiles) {
    constexpr int BM = 64;
    constexpr int NG = BN / 64;           // 64-col groups (2 or 1)
    constexpr int SAS = BM + 4;           // 68: multiple of 4 -> 16B-aligned float4 rows

    extern __shared__ float smem[];
    float* sW  = smem;                    // [128][BN]
    float* sAT = smem + 128 * BN;         // [128][SAS]  A transposed: sAT[k][m]

    const int tid = threadIdx.x;
    const int cx = tid & 15;
    const int tr = tid >> 4;
    const int r0 = tr * 4;

    // stage W once
    {
        const float4* Wv = (const float4*)W;
        float4* sWv = (float4*)sW;
        for (int i = tid; i < 128 * BN / 4; i += 256) sWv[i] = Wv[i];
    }

    float bv[NG][4];
    if (MODE != 0) {
#pragma unroll
        for (int g = 0; g < NG; g++)
#pragma unroll
            for (int j = 0; j < 4; j++) bv[g][j] = __ldg(&bias[g * 64 + cx * 4 + j]);
    }

    for (int tile = blockIdx.x; tile < ntiles; tile += gridDim.x) {
        const int rowbase = tile * BM;
        const int nrows = min(BM, M - rowbase);

        __syncthreads();   // previous iteration's readers done
        // load A tile (64 x 128) transposed into sAT[k][m]
        for (int i = tid; i < BM * 32; i += 256) {
            int r = i >> 5, c4 = i & 31;
            float4 v = make_float4(0.f, 0.f, 0.f, 0.f);
            if (r < nrows)
                v = ((const float4*)(A + (size_t)(rowbase + r) * 128))[c4];
            sAT[(4 * c4 + 0) * SAS + r] = v.x;
            sAT[(4 * c4 + 1) * SAS + r] = v.y;
            sAT[(4 * c4 + 2) * SAS + r] = v.z;
            sAT[(4 * c4 + 3) * SAS + r] = v.w;
        }
        __syncthreads();

        u64 acc[4][NG][2];
#pragma unroll
        for (int i = 0; i < 4; i++)
#pragma unroll
            for (int g = 0; g < NG; g++) { acc[i][g][0] = 0ULL; acc[i][g][1] = 0ULL; }

#pragma unroll 8
        for (int k = 0; k < 128; k++) {
            float4 a4 = *(const float4*)&sAT[k * SAS + r0];
            u64 aa[4];
            PACK_F32X2(aa[0], a4.x, a4.x);
            PACK_F32X2(aa[1], a4.y, a4.y);
            PACK_F32X2(aa[2], a4.z, a4.z);
            PACK_F32X2(aa[3], a4.w, a4.w);
#pragma unroll
            for (int g = 0; g < NG; g++) {
                const u64* w2 = (const u64*)&sW[k * BN + g * 64 + cx * 4];
                u64 w0 = w2[0], w1 = w2[1];
#pragma unroll
                for (int i = 0; i < 4; i++) {
                    FMA_F32X2(acc[i][g][0], aa[i], w0);
                    FMA_F32X2(acc[i][g][1], aa[i], w1);
                }
            }
        }

#pragma unroll
        for (int i = 0; i < 4; i++) {
            const int grow = rowbase + r0 + i;
            if (grow >= M) break;
            const float s = (MODE == 0) ? dinv[grow] : 0.f;
#pragma unroll
            for (int g = 0; g < NG; g++) {
                float v0, v1, v2, v3;
                UNPACK_F32X2(v0, v1, acc[i][g][0]);
                UNPACK_F32X2(v2, v3, acc[i][g][1]);
                float4* o = (float4*)(out1 + (size_t)grow * BN + g * 64 + cx * 4);
                if (MODE == 0) {
                    *o = make_float4(v0 * s, v1 * s, v2 * s, v3 * s);
                } else if (MODE == 1) {
                    *o = make_float4(v0 + bv[g][0], v1 + bv[g][1], v2 + bv[g][2], v3 + bv[g][3]);
                } else {
                    float t0 = v0 + bv[g][0], t1 = v1 + bv[g][1];
                    float t2 = v2 + bv[g][2], t3 = v3 + bv[g][3];
                    *o = make_float4(1.f / (1.f + __expf(-t0)), 1.f / (1.f + __expf(-t1)),
                                     1.f / (1.f + __expf(-t2)), 1.f / (1.f + __expf(-t3)));
                }
            }
        }
    }
}

// ---------------- fused CSR aggregate + self-loop + dinv + bias + ReLU (+LN) ----------------
// one warp per node; lane owns float4 (4 of 128 features)
template <int DO_LN>
__global__ __launch_bounds__(256)
void aggregate_kernel(const float4* __restrict__ z, const int* __restrict__ off,
                      const int* __restrict__ srcs, const float* __restrict__ dinv,
                      const float* __restrict__ b, const float* __restrict__ g,
                      const float* __restrict__ be, float4* __restrict__ out, int n) {
    const int warp = (blockIdx.x * blockDim.x + threadIdx.x) >> 5;
    const int lane = threadIdx.x & 31;
    if (warp >= n) return;

    const int s0 = __ldg(&off[warp]);
    const int s1 = __ldg(&off[warp + 1]);

    float4 acc = __ldg(&z[(size_t)warp * 32 + lane]);   // self loop (z already carries dinv[src])
    for (int base = s0; base < s1; base += 32) {
        const int cnt = min(32, s1 - base);
        int mys = (base + lane < s1) ? __ldg(&srcs[base + lane]) : 0;
#pragma unroll 8
        for (int j = 0; j < cnt; j++) {
            int sn = __shfl_sync(0xffffffffu, mys, j);
            float4 v = __ldg(&z[(size_t)sn * 32 + lane]);
            acc.x += v.x; acc.y += v.y; acc.z += v.z; acc.w += v.w;
        }
    }

    const float dv = __ldg(&dinv[warp]);
    const float4 bb = ((const float4*)b)[lane];
    float4 v = make_float4(fmaxf(fmaf(dv, acc.x, bb.x), 0.f),
                           fmaxf(fmaf(dv, acc.y, bb.y), 0.f),
                           fmaxf(fmaf(dv, acc.z, bb.z), 0.f),
                           fmaxf(fmaf(dv, acc.w, bb.w), 0.f));
    if (DO_LN) {
        float s = v.x + v.y + v.z + v.w;
#pragma unroll
        for (int o = 16; o > 0; o >>= 1) s += __shfl_xor_sync(0xffffffffu, s, o);
        const float mu = s * (1.f / 128.f);
        float4 xc = make_float4(v.x - mu, v.y - mu, v.z - mu, v.w - mu);
        float s2 = xc.x * xc.x + xc.y * xc.y + xc.z * xc.z + xc.w * xc.w;
#pragma unroll
        for (int o = 16; o > 0; o >>= 1) s2 += __shfl_xor_sync(0xffffffffu, s2, o);
        const float rs = rsqrtf(s2 * (1.f / 128.f) + LN_EPS);
        const float4 gg = ((const float4*)g)[lane];
        const float4 ee = ((const float4*)be)[lane];
        v = make_float4(fmaf(gg.x * xc.x, rs, ee.x), fmaf(gg.y * xc.y, rs, ee.y),
                        fmaf(gg.z * xc.z, rs, ee.z), fmaf(gg.w * xc.w, rs, ee.w));
    }
    out[(size_t)warp * 32 + lane] = v;
}

// ---------------- launch ----------------
extern "C" void kernel_launch(void* const* d_in, const int* in_sizes, int n_in,
                              void* d_out, int out_size) {
    const float* x   = (const float*)d_in[0];
    const int*   ei  = (const int*)  d_in[1];
    const float* W1  = (const float*)d_in[2];
    const float* b1  = (const float*)d_in[3];
    const float* W2  = (const float*)d_in[4];
    const float* b2  = (const float*)d_in[5];
    const float* W3  = (const float*)d_in[6];
    const float* b3  = (const float*)d_in[7];
    const float* g1  = (const float*)d_in[8];
    const float* be1 = (const float*)d_in[9];
    const float* g2  = (const float*)d_in[10];
    const float* be2 = (const float*)d_in[11];
    const float* Wp1 = (const float*)d_in[12];
    const float* bp1 = (const float*)d_in[13];
    const float* Wp2 = (const float*)d_in[14];
    const float* bp2 = (const float*)d_in[15];
    float* out = (float*)d_out;

    const int n = in_sizes[0] / DIM;          // 100000
    const int E = in_sizes[1] / 2;            // 1600000
    const int* src = ei;
    const int* dst = ei + E;

    int *deg, *off, *cur, *srcs;
    float *dinv, *bufA, *bufC, *Wf, *bf;
    cudaGetSymbolAddress((void**)&deg,  g_deg);
    cudaGetSymbolAddress((void**)&off,  g_off);
    cudaGetSymbolAddress((void**)&cur,  g_cur);
    cudaGetSymbolAddress((void**)&srcs, g_srcs);
    cudaGetSymbolAddress((void**)&dinv, g_dinv);
    cudaGetSymbolAddress((void**)&bufA, g_bufA);
    cudaGetSymbolAddress((void**)&bufC, g_bufC);
    cudaGetSymbolAddress((void**)&Wf,   g_Wf);
    cudaGetSymbolAddress((void**)&bf,   g_bf);

    const int SMEM128 = (128 * 128 + 128 * 68) * 4;  // 100352 B
    const int SMEM64  = (128 * 64  + 128 * 68) * 4;  // 67584 B
    cudaFuncSetAttribute(gemm_kernel<128, 0>, cudaFuncAttributeMaxDynamicSharedMemorySize, SMEM128);
    cudaFuncSetAttribute(gemm_kernel<64,  2>, cudaFuncAttributeMaxDynamicSharedMemorySize, SMEM64);

    const int ntiles = (n + 63) / 64;                // 1563
    const int GEMM_GRID = 296;                       // 2 blocks/SM
    const int agg_grid = (n * 32 + 255) / 256;       // 1 warp per node

    // ---- CSR build (reused by all 3 convs) + fused head weights ----
    zero_deg_kernel<<<(n + 255) / 256, 256>>>(deg, n);
    hist_kernel<<<(E + 255) / 256, 256>>>(dst, deg, E);
    fuse_heads_kernel<<<33, 256>>>(Wp1, bp1, Wp2, bp2, Wf, bf);
    scan_kernel<<<1, 1024>>>(deg, off, cur, dinv, n);
    bucket_kernel<<<(E + 255) / 256, 256>>>(src, dst, cur, srcs, E);

    // ---- conv1 ----
    gemm_kernel<128, 0><<<GEMM_GRID, 256, SMEM128>>>(x, W1, nullptr, dinv, bufA, n, ntiles);
    aggregate_kernel<1><<<agg_grid, 256>>>((const float4*)bufA, off, srcs, dinv, b1, g1, be1, (float4*)bufC, n);

    // ---- conv2 ----
    gemm_kernel<128, 0><<<GEMM_GRID, 256, SMEM128>>>(bufC, W2, nullptr, dinv, bufA, n, ntiles);
    aggregate_kernel<1><<<agg_grid, 256>>>((const float4*)bufA, off, srcs, dinv, b2, g2, be2, (float4*)bufC, n);

    // ---- conv3 (no LN) ----
    gemm_kernel<128, 0><<<GEMM_GRID, 256, SMEM128>>>(bufC, W3, nullptr, dinv, bufA, n, ntiles);
    aggregate_kernel<0><<<agg_grid, 256>>>((const float4*)bufA, off, srcs, dinv, b3, nullptr, nullptr, (float4*)bufC, n);

    // ---- fused head: out = sigmoid(h @ Wf + bf) ----
    gemm_kernel<64, 2><<<GEMM_GRID, 256, SMEM64>>>(bufC, Wf, bf, nullptr, out, n, ntiles);
}

// round 7
// speedup vs baseline: 1.6244x; 1.3570x over previous
#include <cuda_runtime.h>
#include <math.h>

#define NMAX 100000
#define EMAX 2000000
#define DIM 128
#define LN_EPS 1e-5f

typedef unsigned long long u64;

// ---------------- packed f32x2 helpers (sm_103a) ----------------
#define FMA_F32X2(d, a, b) \
    asm("fma.rn.f32x2 %0, %1, %2, %0;" : "+l"(d) : "l"(a), "l"(b))
#define PACK_F32X2(out, lo, hi) \
    asm("mov.b64 %0, {%1, %2};" : "=l"(out) : "f"(lo), "f"(hi))
#define UNPACK_F32X2(lo, hi, in) \
    asm("mov.b64 {%0, %1}, %2;" : "=f"(lo), "=f"(hi) : "l"(in))

// ---------------- static scratch ----------------
__device__ int   g_deg [NMAX];
__device__ int   g_off [NMAX + 1];
__device__ int   g_cur [NMAX];
__device__ int   g_srcs[EMAX];
__device__ int   g_bsum[256];          // per-block partial sums for the scan
__device__ float g_dinv[NMAX];
__device__ float g_Wf  [DIM * 64];     // fused head weight Wp1@Wp2
__device__ float g_bf  [64];           // fused head bias   bp1@Wp2 + bp2
__device__ float g_bufA[(size_t)NMAX * DIM];   // z = (h @ W) * dinv[row]
__device__ float g_bufC[(size_t)NMAX * DIM];   // layer activations

// ---------------- CSR build ----------------
__global__ void zero_deg_kernel(int* __restrict__ deg, int n) {
    int i = blockIdx.x * blockDim.x + threadIdx.x;
    if (i < n) deg[i] = 0;
}

__global__ void hist_kernel(const int* __restrict__ dst, int* __restrict__ deg, int E) {
    int e = blockIdx.x * blockDim.x + threadIdx.x;
    if (e < E) atomicAdd(&deg[dst[e]], 1);
}

// ---- 3-phase parallel exclusive scan over deg (1024 elems per block) ----
__global__ __launch_bounds__(256)
void scan_part_kernel(const int* __restrict__ deg, int* __restrict__ bsum, int n) {
    const int tid = threadIdx.x;
    const int base = blockIdx.x * 1024 + tid * 4;
    int s = 0;
#pragma unroll
    for (int i = 0; i < 4; i++) {
        int idx = base + i;
        if (idx < n) s += deg[idx];
    }
#pragma unroll
    for (int o = 16; o > 0; o >>= 1) s += __shfl_xor_sync(0xffffffffu, s, o);
    __shared__ int ws[8];
    if ((tid & 31) == 0) ws[tid >> 5] = s;
    __syncthreads();
    if (tid == 0) {
        int t = 0;
#pragma unroll
        for (int i = 0; i < 8; i++) t += ws[i];
        bsum[blockIdx.x] = t;
    }
}

__global__ __launch_bounds__(128)
void scan_block_kernel(int* __restrict__ bsum, int nb) {
    __shared__ int sh[128];
    const int tid = threadIdx.x;
    int v = (tid < nb) ? bsum[tid] : 0;
    sh[tid] = v;
    __syncthreads();
    for (int o = 1; o < 128; o <<= 1) {
        int t = (tid >= o) ? sh[tid - o] : 0;
        __syncthreads();
        sh[tid] += t;
        __syncthreads();
    }
    if (tid < nb) bsum[tid] = sh[tid] - v;   // exclusive
}

__global__ __launch_bounds__(256)
void scan_final_kernel(const int* __restrict__ deg, const int* __restrict__ bsum,
                       int* __restrict__ off, int* __restrict__ cur,
                       float* __restrict__ dinv, int n) {
    const int tid = threadIdx.x;
    const int lane = tid & 31, w = tid >> 5;
    const int base = blockIdx.x * 1024 + tid * 4;
    int d[4];
    int s = 0;
#pragma unroll
    for (int i = 0; i < 4; i++) {
        int idx = base + i;
        d[i] = (idx < n) ? deg[idx] : 0;
        s += d[i];
    }
    // inclusive warp scan of s
    int inc = s;
#pragma unroll
    for (int o = 1; o < 32; o <<= 1) {
        int t = __shfl_up_sync(0xffffffffu, inc, o);
        if (lane >= o) inc += t;
    }
    __shared__ int ws[8];
    if (lane == 31) ws[w] = inc;
    __syncthreads();
    if (w == 0 && lane < 8) {
        int v = ws[lane];
#pragma unroll
        for (int o = 1; o < 8; o <<= 1) {
            int t = __shfl_up_sync(0x000000ffu, v, o);
            if (lane >= o) v += t;
        }
        ws[lane] = v;   // inclusive warp-sum scan
    }
    __syncthreads();
    int run = inc - s + (w > 0 ? ws[w - 1] : 0) + bsum[blockIdx.x];
#pragma unroll
    for (int i = 0; i < 4; i++) {
        int idx = base + i;
        if (idx < n) {
            off[idx] = run;
            cur[idx] = run;
            dinv[idx] = rsqrtf((float)d[i] + 1.0f);
            run += d[i];
            if (idx == n - 1) off[n] = run;
        }
    }
}

__global__ void bucket_kernel(const int* __restrict__ src, const int* __restrict__ dst,
                              int* __restrict__ cur, int* __restrict__ sorted, int E) {
    int e = blockIdx.x * blockDim.x + threadIdx.x;
    if (e < E) {
        int p = atomicAdd(&cur[dst[e]], 1);
        sorted[p] = src[e];
    }
}

// ---------------- fuse heads: Wf = Wp1 @ Wp2, bf = bp1 @ Wp2 + bp2 ----------------
__global__ void fuse_heads_kernel(const float* __restrict__ Wp1, const float* __restrict__ bp1,
                                  const float* __restrict__ Wp2, const float* __restrict__ bp2,
                                  float* __restrict__ Wf, float* __restrict__ bf) {
    int idx = blockIdx.x * blockDim.x + threadIdx.x;
    if (idx < 128 * 64) {
        int i = idx >> 6, j = idx & 63;
        float s = 0.f;
#pragma unroll 8
        for (int k = 0; k < 128; k++)
            s = fmaf(__ldg(&Wp1[i * 128 + k]), __ldg(&Wp2[k * 64 + j]), s);
        Wf[idx] = s;
    } else if (idx < 128 * 64 + 64) {
        int j = idx - 128 * 64;
        float s = __ldg(&bp2[j]);
#pragma unroll 8
        for (int k = 0; k < 128; k++)
            s = fmaf(__ldg(&bp1[k]), __ldg(&Wp2[k * 64 + j]), s);
        bf[j] = s;
    }
}

// ---------------- persistent GEMM: out = A[M,128] @ W[128,BN] ----------------
// 296 blocks x 256 threads (2/SM); W staged once; BM=64 row tiles.
// MODE 0: v *= dinv[row]    MODE 1: v += bias    MODE 2: v = sigmoid(v + bias)
template <int BN, int MODE>
__global__ __launch_bounds__(256)
void gemm_kernel(const float* __restrict__ A, const float* __restrict__ W,
                 const float* __restrict__ bias, const float* __restrict__ dinv,
                 float* __restrict__ out1, int M, int ntiles) {
    constexpr int BM = 64;
    constexpr int NG = BN / 64;
    constexpr int SAS = BM + 4;           // 68: multiple of 4 -> 16B-aligned float4 rows

    extern __shared__ float smem[];
    float* sW  = smem;                    // [128][BN]
    float* sAT = smem + 128 * BN;         // [128][SAS]

    const int tid = threadIdx.x;
    const int cx = tid & 15;
    const int tr = tid >> 4;
    const int r0 = tr * 4;

    {
        const float4* Wv = (const float4*)W;
        float4* sWv = (float4*)sW;
        for (int i = tid; i < 128 * BN / 4; i += 256) sWv[i] = Wv[i];
    }

    float bv[NG][4];
    if (MODE != 0) {
#pragma unroll
        for (int g = 0; g < NG; g++)
#pragma unroll
            for (int j = 0; j < 4; j++) bv[g][j] = __ldg(&bias[g * 64 + cx * 4 + j]);
    }

    for (int tile = blockIdx.x; tile < ntiles; tile += gridDim.x) {
        const int rowbase = tile * BM;
        const int nrows = min(BM, M - rowbase);

        __syncthreads();
        for (int i = tid; i < BM * 32; i += 256) {
            int r = i >> 5, c4 = i & 31;
            float4 v = make_float4(0.f, 0.f, 0.f, 0.f);
            if (r < nrows)
                v = ((const float4*)(A + (size_t)(rowbase + r) * 128))[c4];
            sAT[(4 * c4 + 0) * SAS + r] = v.x;
            sAT[(4 * c4 + 1) * SAS + r] = v.y;
            sAT[(4 * c4 + 2) * SAS + r] = v.z;
            sAT[(4 * c4 + 3) * SAS + r] = v.w;
        }
        __syncthreads();

        u64 acc[4][NG][2];
#pragma unroll
        for (int i = 0; i < 4; i++)
#pragma unroll
            for (int g = 0; g < NG; g++) { acc[i][g][0] = 0ULL; acc[i][g][1] = 0ULL; }

#pragma unroll 8
        for (int k = 0; k < 128; k++) {
            float4 a4 = *(const float4*)&sAT[k * SAS + r0];
            u64 aa[4];
            PACK_F32X2(aa[0], a4.x, a4.x);
            PACK_F32X2(aa[1], a4.y, a4.y);
            PACK_F32X2(aa[2], a4.z, a4.z);
            PACK_F32X2(aa[3], a4.w, a4.w);
#pragma unroll
            for (int g = 0; g < NG; g++) {
                const u64* w2 = (const u64*)&sW[k * BN + g * 64 + cx * 4];
                u64 w0 = w2[0], w1 = w2[1];
#pragma unroll
                for (int i = 0; i < 4; i++) {
                    FMA_F32X2(acc[i][g][0], aa[i], w0);
                    FMA_F32X2(acc[i][g][1], aa[i], w1);
                }
            }
        }

#pragma unroll
        for (int i = 0; i < 4; i++) {
            const int grow = rowbase + r0 + i;
            if (grow >= M) break;
            const float s = (MODE == 0) ? dinv[grow] : 0.f;
#pragma unroll
            for (int g = 0; g < NG; g++) {
                float v0, v1, v2, v3;
                UNPACK_F32X2(v0, v1, acc[i][g][0]);
                UNPACK_F32X2(v2, v3, acc[i][g][1]);
                float4* o = (float4*)(out1 + (size_t)grow * BN + g * 64 + cx * 4);
                if (MODE == 0) {
                    *o = make_float4(v0 * s, v1 * s, v2 * s, v3 * s);
                } else if (MODE == 1) {
                    *o = make_float4(v0 + bv[g][0], v1 + bv[g][1], v2 + bv[g][2], v3 + bv[g][3]);
                } else {
                    float t0 = v0 + bv[g][0], t1 = v1 + bv[g][1];
                    float t2 = v2 + bv[g][2], t3 = v3 + bv[g][3];
                    *o = make_float4(1.f / (1.f + __expf(-t0)), 1.f / (1.f + __expf(-t1)),
                                     1.f / (1.f + __expf(-t2)), 1.f / (1.f + __expf(-t3)));
                }
            }
        }
    }
}

// ---------------- fused CSR aggregate + self-loop + dinv + bias + ReLU (+LN) ----------------
template <int DO_LN>
__global__ __launch_bounds__(256)
void aggregate_kernel(const float4* __restrict__ z, const int* __restrict__ off,
                      const int* __restrict__ srcs, const float* __restrict__ dinv,
                      const float* __restrict__ b, const float* __restrict__ g,
                      const float* __restrict__ be, float4* __restrict__ out, int n) {
    const int warp = (blockIdx.x * blockDim.x + threadIdx.x) >> 5;
    const int lane = threadIdx.x & 31;
    if (warp >= n) return;

    const int s0 = __ldg(&off[warp]);
    const int s1 = __ldg(&off[warp + 1]);

    float4 acc = __ldg(&z[(size_t)warp * 32 + lane]);   // self loop
    for (int base = s0; base < s1; base += 32) {
        const int cnt = min(32, s1 - base);
        int mys = (base + lane < s1) ? __ldg(&srcs[base + lane]) : 0;
#pragma unroll 8
        for (int j = 0; j < cnt; j++) {
            int sn = __shfl_sync(0xffffffffu, mys, j);
            float4 v = __ldg(&z[(size_t)sn * 32 + lane]);
            acc.x += v.x; acc.y += v.y; acc.z += v.z; acc.w += v.w;
        }
    }

    const float dv = __ldg(&dinv[warp]);
    const float4 bb = ((const float4*)b)[lane];
    float4 v = make_float4(fmaxf(fmaf(dv, acc.x, bb.x), 0.f),
                           fmaxf(fmaf(dv, acc.y, bb.y), 0.f),
                           fmaxf(fmaf(dv, acc.z, bb.z), 0.f),
                           fmaxf(fmaf(dv, acc.w, bb.w), 0.f));
    if (DO_LN) {
        float s = v.x + v.y + v.z + v.w;
#pragma unroll
        for (int o = 16; o > 0; o >>= 1) s += __shfl_xor_sync(0xffffffffu, s, o);
        const float mu = s * (1.f / 128.f);
        float4 xc = make_float4(v.x - mu, v.y - mu, v.z - mu, v.w - mu);
        float s2 = xc.x * xc.x + xc.y * xc.y + xc.z * xc.z + xc.w * xc.w;
#pragma unroll
        for (int o = 16; o > 0; o >>= 1) s2 += __shfl_xor_sync(0xffffffffu, s2, o);
        const float rs = rsqrtf(s2 * (1.f / 128.f) + LN_EPS);
        const float4 gg = ((const float4*)g)[lane];
        const float4 ee = ((const float4*)be)[lane];
        v = make_float4(fmaf(gg.x * xc.x, rs, ee.x), fmaf(gg.y * xc.y, rs, ee.y),
                        fmaf(gg.z * xc.z, rs, ee.z), fmaf(gg.w * xc.w, rs, ee.w));
    }
    out[(size_t)warp * 32 + lane] = v;
}

// ---------------- launch ----------------
extern "C" void kernel_launch(void* const* d_in, const int* in_sizes, int n_in,
                              void* d_out, int out_size) {
    const float* x   = (const float*)d_in[0];
    const int*   ei  = (const int*)  d_in[1];
    const float* W1  = (const float*)d_in[2];
    const float* b1  = (const float*)d_in[3];
    const float* W2  = (const float*)d_in[4];
    const float* b2  = (const float*)d_in[5];
    const float* W3  = (const float*)d_in[6];
    const float* b3  = (const float*)d_in[7];
    const float* g1  = (const float*)d_in[8];
    const float* be1 = (const float*)d_in[9];
    const float* g2  = (const float*)d_in[10];
    const float* be2 = (const float*)d_in[11];
    const float* Wp1 = (const float*)d_in[12];
    const float* bp1 = (const float*)d_in[13];
    const float* Wp2 = (const float*)d_in[14];
    const float* bp2 = (const float*)d_in[15];
    float* out = (float*)d_out;

    const int n = in_sizes[0] / DIM;          // 100000
    const int E = in_sizes[1] / 2;            // 1600000
    const int* src = ei;
    const int* dst = ei + E;

    int *deg, *off, *cur, *srcs, *bsum;
    float *dinv, *bufA, *bufC, *Wf, *bf;
    cudaGetSymbolAddress((void**)&deg,  g_deg);
    cudaGetSymbolAddress((void**)&off,  g_off);
    cudaGetSymbolAddress((void**)&cur,  g_cur);
    cudaGetSymbolAddress((void**)&srcs, g_srcs);
    cudaGetSymbolAddress((void**)&bsum, g_bsum);
    cudaGetSymbolAddress((void**)&dinv, g_dinv);
    cudaGetSymbolAddress((void**)&bufA, g_bufA);
    cudaGetSymbolAddress((void**)&bufC, g_bufC);
    cudaGetSymbolAddress((void**)&Wf,   g_Wf);
    cudaGetSymbolAddress((void**)&bf,   g_bf);

    const int SMEM128 = (128 * 128 + 128 * 68) * 4;  // 100352 B
    const int SMEM64  = (128 * 64  + 128 * 68) * 4;  // 67584 B
    cudaFuncSetAttribute(gemm_kernel<128, 0>, cudaFuncAttributeMaxDynamicSharedMemorySize, SMEM128);
    cudaFuncSetAttribute(gemm_kernel<64,  2>, cudaFuncAttributeMaxDynamicSharedMemorySize, SMEM64);

    const int ntiles = (n + 63) / 64;                // 1563
    const int GEMM_GRID = 296;                       // 2 blocks/SM
    const int agg_grid = (n * 32 + 255) / 256;       // 1 warp per node
    const int nscan = (n + 1023) / 1024;             // 98 scan blocks

    // ---- CSR build (reused by all 3 convs) + fused head weights ----
    zero_deg_kernel<<<(n + 255) / 256, 256>>>(deg, n);
    hist_kernel<<<(E + 255) / 256, 256>>>(dst, deg, E);
    fuse_heads_kernel<<<33, 256>>>(Wp1, bp1, Wp2, bp2, Wf, bf);
    scan_part_kernel <<<nscan, 256>>>(deg, bsum, n);
    scan_block_kernel<<<1, 128>>>(bsum, nscan);
    scan_final_kernel<<<nscan, 256>>>(deg, bsum, off, cur, dinv, n);
    bucket_kernel<<<(E + 255) / 256, 256>>>(src, dst, cur, srcs, E);

    // ---- conv1 ----
    gemm_kernel<128, 0><<<GEMM_GRID, 256, SMEM128>>>(x, W1, nullptr, dinv, bufA, n, ntiles);
    aggregate_kernel<1><<<agg_grid, 256>>>((const float4*)bufA, off, srcs, dinv, b1, g1, be1, (float4*)bufC, n);

    // ---- conv2 ----
    gemm_kernel<128, 0><<<GEMM_GRID, 256, SMEM128>>>(bufC, W2, nullptr, dinv, bufA, n, ntiles);
    aggregate_kernel<1><<<agg_grid, 256>>>((const float4*)bufA, off, srcs, dinv, b2, g2, be2, (float4*)bufC, n);

    // ---- conv3 (no LN) ----
    gemm_kernel<128, 0><<<GEMM_GRID, 256, SMEM128>>>(bufC, W3, nullptr, dinv, bufA, n, ntiles);
    aggregate_kernel<0><<<agg_grid, 256>>>((const float4*)bufA, off, srcs, dinv, b3, nullptr, nullptr, (float4*)bufC, n);

    // ---- fused head: out = sigmoid(h @ Wf + bf) ----
    gemm_kernel<64, 2><<<GEMM_GRID, 256, SMEM64>>>(bufC, Wf, bf, nullptr, out, n, ntiles);
}

// round 8
// speedup vs baseline: 1.6320x; 1.0047x over previous
#include <cuda_runtime.h>
#include <math.h>

#define NMAX 100000
#define EMAX 2000000
#define DIM 128
#define LN_EPS 1e-5f

typedef unsigned long long u64;

// ---------------- packed f32x2 helpers (sm_103a) ----------------
#define FMA_F32X2(d, a, b) \
    asm("fma.rn.f32x2 %0, %1, %2, %0;" : "+l"(d) : "l"(a), "l"(b))
#define PACK_F32X2(out, lo, hi) \
    asm("mov.b64 %0, {%1, %2};" : "=l"(out) : "f"(lo), "f"(hi))
#define UNPACK_F32X2(lo, hi, in) \
    asm("mov.b64 {%0, %1}, %2;" : "=f"(lo), "=f"(hi) : "l"(in))

// ---------------- static scratch ----------------
__device__ int   g_deg [NMAX];
__device__ int   g_off [NMAX + 1];
__device__ int   g_cur [NMAX];
__device__ int   g_srcs[EMAX];
__device__ int   g_bsum[256];
__device__ float g_dinv[NMAX];
__device__ float g_Wf  [DIM * 64];
__device__ float g_bf  [64];
__device__ float g_bufA[(size_t)NMAX * DIM];   // z = (h @ W) * dinv[row]
__device__ float g_bufC[(size_t)NMAX * DIM];   // layer activations

// ---------------- CSR build ----------------
__global__ void zero_deg_kernel(int* __restrict__ deg, int n) {
    int i = blockIdx.x * blockDim.x + threadIdx.x;
    if (i < n) deg[i] = 0;
}

__global__ void hist_kernel(const int* __restrict__ dst, int* __restrict__ deg, int E) {
    int e = blockIdx.x * blockDim.x + threadIdx.x;
    if (e < E) atomicAdd(&deg[dst[e]], 1);
}

__global__ __launch_bounds__(256)
void scan_part_kernel(const int* __restrict__ deg, int* __restrict__ bsum, int n) {
    const int tid = threadIdx.x;
    const int base = blockIdx.x * 1024 + tid * 4;
    int s = 0;
#pragma unroll
    for (int i = 0; i < 4; i++) {
        int idx = base + i;
        if (idx < n) s += deg[idx];
    }
#pragma unroll
    for (int o = 16; o > 0; o >>= 1) s += __shfl_xor_sync(0xffffffffu, s, o);
    __shared__ int ws[8];
    if ((tid & 31) == 0) ws[tid >> 5] = s;
    __syncthreads();
    if (tid == 0) {
        int t = 0;
#pragma unroll
        for (int i = 0; i < 8; i++) t += ws[i];
        bsum[blockIdx.x] = t;
    }
}

__global__ __launch_bounds__(128)
void scan_block_kernel(int* __restrict__ bsum, int nb) {
    __shared__ int sh[128];
    const int tid = threadIdx.x;
    int v = (tid < nb) ? bsum[tid] : 0;
    sh[tid] = v;
    __syncthreads();
    for (int o = 1; o < 128; o <<= 1) {
        int t = (tid >= o) ? sh[tid - o] : 0;
        __syncthreads();
        sh[tid] += t;
        __syncthreads();
    }
    if (tid < nb) bsum[tid] = sh[tid] - v;   // exclusive
}

__global__ __launch_bounds__(256)
void scan_final_kernel(const int* __restrict__ deg, const int* __restrict__ bsum,
                       int* __restrict__ off, int* __restrict__ cur,
                       float* __restrict__ dinv, int n) {
    const int tid = threadIdx.x;
    const int lane = tid & 31, w = tid >> 5;
    const int base = blockIdx.x * 1024 + tid * 4;
    int d[4];
    int s = 0;
#pragma unroll
    for (int i = 0; i < 4; i++) {
        int idx = base + i;
        d[i] = (idx < n) ? deg[idx] : 0;
        s += d[i];
    }
    int inc = s;
#pragma unroll
    for (int o = 1; o < 32; o <<= 1) {
        int t = __shfl_up_sync(0xffffffffu, inc, o);
        if (lane >= o) inc += t;
    }
    __shared__ int ws[8];
    if (lane == 31) ws[w] = inc;
    __syncthreads();
    if (w == 0 && lane < 8) {
        int v = ws[lane];
#pragma unroll
        for (int o = 1; o < 8; o <<= 1) {
            int t = __shfl_up_sync(0x000000ffu, v, o);
            if (lane >= o) v += t;
        }
        ws[lane] = v;
    }
    __syncthreads();
    int run = inc - s + (w > 0 ? ws[w - 1] : 0) + bsum[blockIdx.x];
#pragma unroll
    for (int i = 0; i < 4; i++) {
        int idx = base + i;
        if (idx < n) {
            off[idx] = run;
            cur[idx] = run;
            dinv[idx] = rsqrtf((float)d[i] + 1.0f);
            run += d[i];
            if (idx == n - 1) off[n] = run;
        }
    }
}

__global__ void bucket_kernel(const int* __restrict__ src, const int* __restrict__ dst,
                              int* __restrict__ cur, int* __restrict__ sorted, int E) {
    int e = blockIdx.x * blockDim.x + threadIdx.x;
    if (e < E) {
        int p = atomicAdd(&cur[dst[e]], 1);
        sorted[p] = src[e];
    }
}

// ---------------- fuse heads: Wf = Wp1 @ Wp2, bf = bp1 @ Wp2 + bp2 ----------------
__global__ void fuse_heads_kernel(const float* __restrict__ Wp1, const float* __restrict__ bp1,
                                  const float* __restrict__ Wp2, const float* __restrict__ bp2,
                                  float* __restrict__ Wf, float* __restrict__ bf) {
    int idx = blockIdx.x * blockDim.x + threadIdx.x;
    if (idx < 128 * 64) {
        int i = idx >> 6, j = idx & 63;
        float s = 0.f;
#pragma unroll 8
        for (int k = 0; k < 128; k++)
            s = fmaf(__ldg(&Wp1[i * 128 + k]), __ldg(&Wp2[k * 64 + j]), s);
        Wf[idx] = s;
    } else if (idx < 128 * 64 + 64) {
        int j = idx - 128 * 64;
        float s = __ldg(&bp2[j]);
#pragma unroll 8
        for (int k = 0; k < 128; k++)
            s = fmaf(__ldg(&bp1[k]), __ldg(&Wp2[k * 64 + j]), s);
        bf[j] = s;
    }
}

// ---------------- persistent GEMM with register double-buffered A staging ----------------
// out = A[M,128] @ W[128,BN]; 296 blocks x 256 threads (2/SM); W staged once.
// MODE 0: v *= dinv[row]    MODE 1: v += bias    MODE 2: v = sigmoid(v + bias)
template <int BN, int MODE>
__global__ __launch_bounds__(256)
void gemm_kernel(const float* __restrict__ A, const float* __restrict__ W,
                 const float* __restrict__ bias, const float* __restrict__ dinv,
                 float* __restrict__ out1, int M, int ntiles) {
    constexpr int BM = 64;
    constexpr int NG = BN / 64;
    constexpr int SAS = BM + 4;           // 68: multiple of 4 -> 16B-aligned float4 rows

    extern __shared__ float smem[];
    float* sW  = smem;                    // [128][BN]
    float* sAT = smem + 128 * BN;         // [128][SAS]

    const int tid = threadIdx.x;
    const int cx = tid & 15;
    const int tr = tid >> 4;
    const int r0 = tr * 4;

    {
        const float4* Wv = (const float4*)W;
        float4* sWv = (float4*)sW;
        for (int i = tid; i < 128 * BN / 4; i += 256) sWv[i] = Wv[i];
    }

    float bv[NG][4];
    if (MODE != 0) {
#pragma unroll
        for (int g = 0; g < NG; g++)
#pragma unroll
            for (int j = 0; j < 4; j++) bv[g][j] = __ldg(&bias[g * 64 + cx * 4 + j]);
    }

    // prefetch registers: 8 float4 per thread covers the 64x128 tile
    float4 pf[8];

#define LOAD_TILE(TILE)                                                            \
    {                                                                              \
        const int rb_ = (TILE) * BM;                                               \
        const int nr_ = min(BM, M - rb_);                                          \
        _Pragma("unroll")                                                          \
        for (int i_ = 0; i_ < 8; i_++) {                                           \
            int idx_ = tid + i_ * 256;                                             \
            int r_ = idx_ >> 5, c4_ = idx_ & 31;                                   \
            pf[i_] = (r_ < nr_)                                                    \
                ? ((const float4*)(A + (size_t)(rb_ + r_) * 128))[c4_]             \
                : make_float4(0.f, 0.f, 0.f, 0.f);                                 \
        }                                                                          \
    }

    if (blockIdx.x < ntiles) LOAD_TILE(blockIdx.x);

    for (int tile = blockIdx.x; tile < ntiles; tile += gridDim.x) {
        __syncthreads();   // previous iteration's readers done with sAT
        // store prefetched A (transposed) to smem
#pragma unroll
        for (int i = 0; i < 8; i++) {
            int idx = tid + i * 256;
            int r = idx >> 5, c4 = idx & 31;
            sAT[(4 * c4 + 0) * SAS + r] = pf[i].x;
            sAT[(4 * c4 + 1) * SAS + r] = pf[i].y;
            sAT[(4 * c4 + 2) * SAS + r] = pf[i].z;
            sAT[(4 * c4 + 3) * SAS + r] = pf[i].w;
        }
        __syncthreads();

        // issue next tile's loads now; latency hidden behind compute
        const int next = tile + gridDim.x;
        if (next < ntiles) LOAD_TILE(next);

        u64 acc[4][NG][2];
#pragma unroll
        for (int i = 0; i < 4; i++)
#pragma unroll
            for (int g = 0; g < NG; g++) { acc[i][g][0] = 0ULL; acc[i][g][1] = 0ULL; }

#pragma unroll 8
        for (int k = 0; k < 128; k++) {
            float4 a4 = *(const float4*)&sAT[k * SAS + r0];
            u64 aa[4];
            PACK_F32X2(aa[0], a4.x, a4.x);
            PACK_F32X2(aa[1], a4.y, a4.y);
            PACK_F32X2(aa[2], a4.z, a4.z);
            PACK_F32X2(aa[3], a4.w, a4.w);
#pragma unroll
            for (int g = 0; g < NG; g++) {
                const u64* w2 = (const u64*)&sW[k * BN + g * 64 + cx * 4];
                u64 w0 = w2[0], w1 = w2[1];
#pragma unroll
                for (int i = 0; i < 4; i++) {
                    FMA_F32X2(acc[i][g][0], aa[i], w0);
                    FMA_F32X2(acc[i][g][1], aa[i], w1);
                }
            }
        }

        const int rowbase = tile * BM;
#pragma unroll
        for (int i = 0; i < 4; i++) {
            const int grow = rowbase + r0 + i;
            if (grow >= M) break;
            const float s = (MODE == 0) ? dinv[grow] : 0.f;
#pragma unroll
            for (int g = 0; g < NG; g++) {
                float v0, v1, v2, v3;
                UNPACK_F32X2(v0, v1, acc[i][g][0]);
                UNPACK_F32X2(v2, v3, acc[i][g][1]);
                float4* o = (float4*)(out1 + (size_t)grow * BN + g * 64 + cx * 4);
                if (MODE == 0) {
                    *o = make_float4(v0 * s, v1 * s, v2 * s, v3 * s);
                } else if (MODE == 1) {
                    *o = make_float4(v0 + bv[g][0], v1 + bv[g][1], v2 + bv[g][2], v3 + bv[g][3]);
                } else {
                    float t0 = v0 + bv[g][0], t1 = v1 + bv[g][1];
                    float t2 = v2 + bv[g][2], t3 = v3 + bv[g][3];
                    *o = make_float4(1.f / (1.f + __expf(-t0)), 1.f / (1.f + __expf(-t1)),
                                     1.f / (1.f + __expf(-t2)), 1.f / (1.f + __expf(-t3)));
                }
            }
        }
    }
#undef LOAD_TILE
}

// ---------------- fused CSR aggregate + self-loop + dinv + bias + ReLU (+LN) ----------------
template <int DO_LN>
__global__ __launch_bounds__(256)
void aggregate_kernel(const float4* __restrict__ z, const int* __restrict__ off,
                      const int* __restrict__ srcs, const float* __restrict__ dinv,
                      const float* __restrict__ b, const float* __restrict__ g,
                      const float* __restrict__ be, float4* __restrict__ out, int n) {
    const int warp = (blockIdx.x * blockDim.x + threadIdx.x) >> 5;
    const int lane = threadIdx.x & 31;
    if (warp >= n) return;

    const int s0 = __ldg(&off[warp]);
    const int s1 = __ldg(&off[warp + 1]);

    float4 acc = __ldg(&z[(size_t)warp * 32 + lane]);   // self loop
    for (int base = s0; base < s1; base += 32) {
        const int cnt = min(32, s1 - base);
        int mys = (base + lane < s1) ? __ldg(&srcs[base + lane]) : 0;
#pragma unroll 8
        for (int j = 0; j < cnt; j++) {
            int sn = __shfl_sync(0xffffffffu, mys, j);
            float4 v = __ldg(&z[(size_t)sn * 32 + lane]);
            acc.x += v.x; acc.y += v.y; acc.z += v.z; acc.w += v.w;
        }
    }

    const float dv = __ldg(&dinv[warp]);
    const float4 bb = ((const float4*)b)[lane];
    float4 v = make_float4(fmaxf(fmaf(dv, acc.x, bb.x), 0.f),
                           fmaxf(fmaf(dv, acc.y, bb.y), 0.f),
                           fmaxf(fmaf(dv, acc.z, bb.z), 0.f),
                           fmaxf(fmaf(dv, acc.w, bb.w), 0.f));
    if (DO_LN) {
        float s = v.x + v.y + v.z + v.w;
#pragma unroll
        for (int o = 16; o > 0; o >>= 1) s += __shfl_xor_sync(0xffffffffu, s, o);
        const float mu = s * (1.f / 128.f);
        float4 xc = make_float4(v.x - mu, v.y - mu, v.z - mu, v.w - mu);
        float s2 = xc.x * xc.x + xc.y * xc.y + xc.z * xc.z + xc.w * xc.w;
#pragma unroll
        for (int o = 16; o > 0; o >>= 1) s2 += __shfl_xor_sync(0xffffffffu, s2, o);
        const float rs = rsqrtf(s2 * (1.f / 128.f) + LN_EPS);
        const float4 gg = ((const float4*)g)[lane];
        const float4 ee = ((const float4*)be)[lane];
        v = make_float4(fmaf(gg.x * xc.x, rs, ee.x), fmaf(gg.y * xc.y, rs, ee.y),
                        fmaf(gg.z * xc.z, rs, ee.z), fmaf(gg.w * xc.w, rs, ee.w));
    }
    out[(size_t)warp * 32 + lane] = v;
}

// ---------------- launch ----------------
extern "C" void kernel_launch(void* const* d_in, const int* in_sizes, int n_in,
                              void* d_out, int out_size) {
    const float* x   = (const float*)d_in[0];
    const int*   ei  = (const int*)  d_in[1];
    const float* W1  = (const float*)d_in[2];
    const float* b1  = (const float*)d_in[3];
    const float* W2  = (const float*)d_in[4];
    const float* b2  = (const float*)d_in[5];
    const float* W3  = (const float*)d_in[6];
    const float* b3  = (const float*)d_in[7];
    const float* g1  = (const float*)d_in[8];
    const float* be1 = (const float*)d_in[9];
    const float* g2  = (const float*)d_in[10];
    const float* be2 = (const float*)d_in[11];
    const float* Wp1 = (const float*)d_in[12];
    const float* bp1 = (const float*)d_in[13];
    const float* Wp2 = (const float*)d_in[14];
    const float* bp2 = (const float*)d_in[15];
    float* out = (float*)d_out;

    const int n = in_sizes[0] / DIM;          // 100000
    const int E = in_sizes[1] / 2;            // 1600000
    const int* src = ei;
    const int* dst = ei + E;

    int *deg, *off, *cur, *srcs, *bsum;
    float *dinv, *bufA, *bufC, *Wf, *bf;
    cudaGetSymbolAddress((void**)&deg,  g_deg);
    cudaGetSymbolAddress((void**)&off,  g_off);
    cudaGetSymbolAddress((void**)&cur,  g_cur);
    cudaGetSymbolAddress((void**)&srcs, g_srcs);
    cudaGetSymbolAddress((void**)&bsum, g_bsum);
    cudaGetSymbolAddress((void**)&dinv, g_dinv);
    cudaGetSymbolAddress((void**)&bufA, g_bufA);
    cudaGetSymbolAddress((void**)&bufC, g_bufC);
    cudaGetSymbolAddress((void**)&Wf,   g_Wf);
    cudaGetSymbolAddress((void**)&bf,   g_bf);

    const int SMEM128 = (128 * 128 + 128 * 68) * 4;  // 100352 B
    const int SMEM64  = (128 * 64  + 128 * 68) * 4;  // 67584 B
    cudaFuncSetAttribute(gemm_kernel<128, 0>, cudaFuncAttributeMaxDynamicSharedMemorySize, SMEM128);
    cudaFuncSetAttribute(gemm_kernel<64,  2>, cudaFuncAttributeMaxDynamicSharedMemorySize, SMEM64);

    const int ntiles = (n + 63) / 64;                // 1563
    const int GEMM_GRID = 296;                       // 2 blocks/SM
    const int agg_grid = (n * 32 + 255) / 256;       // 1 warp per node
    const int nscan = (n + 1023) / 1024;             // 98 scan blocks

    // ---- CSR build (reused by all 3 convs) + fused head weights ----
    zero_deg_kernel<<<(n + 255) / 256, 256>>>(deg, n);
    hist_kernel<<<(E + 255) / 256, 256>>>(dst, deg, E);
    fuse_heads_kernel<<<33, 256>>>(Wp1, bp1, Wp2, bp2, Wf, bf);
    scan_part_kernel <<<nscan, 256>>>(deg, bsum, n);
    scan_block_kernel<<<1, 128>>>(bsum, nscan);
    scan_final_kernel<<<nscan, 256>>>(deg, bsum, off, cur, dinv, n);
    bucket_kernel<<<(E + 255) / 256, 256>>>(src, dst, cur, srcs, E);

    // ---- conv1 ----
    gemm_kernel<128, 0><<<GEMM_GRID, 256, SMEM128>>>(x, W1, nullptr, dinv, bufA, n, ntiles);
    aggregate_kernel<1><<<agg_grid, 256>>>((const float4*)bufA, off, srcs, dinv, b1, g1, be1, (float4*)bufC, n);

    // ---- conv2 ----
    gemm_kernel<128, 0><<<GEMM_GRID, 256, SMEM128>>>(bufC, W2, nullptr, dinv, bufA, n, ntiles);
    aggregate_kernel<1><<<agg_grid, 256>>>((const float4*)bufA, off, srcs, dinv, b2, g2, be2, (float4*)bufC, n);

    // ---- conv3 (no LN) ----
    gemm_kernel<128, 0><<<GEMM_GRID, 256, SMEM128>>>(bufC, W3, nullptr, dinv, bufA, n, ntiles);
    aggregate_kernel<0><<<agg_grid, 256>>>((const float4*)bufA, off, srcs, dinv, b3, nullptr, nullptr, (float4*)bufC, n);

    // ---- fused head: out = sigmoid(h @ Wf + bf) ----
    gemm_kernel<64, 2><<<GEMM_GRID, 256, SMEM64>>>(bufC, Wf, bf, nullptr, out, n, ntiles);
}

// round 10
// speedup vs baseline: 2.2399x; 1.3724x over previous
#include <cuda_runtime.h>
#include <cuda_bf16.h>
#include <math.h>
#include <stdint.h>

#define NMAX 100000
#define EMAX 2000000
#define DIM 128
#define LN_EPS 1e-5f

// ---------------- helpers ----------------
__device__ __forceinline__ uint32_t smem_to_u32(const void* p) {
    uint32_t a;
    asm("{ .reg .u64 t; cvta.to.shared.u64 t, %1; cvt.u32.u64 %0, t; }" : "=r"(a) : "l"(p));
    return a;
}
// pack two fp32 -> bf16x2 (upper = hi arg, lower = lo arg)
#define CVT_PACK(res, up, low) \
    asm("cvt.rn.bf16x2.f32 %0, %1, %2;" : "=r"(res) : "f"(up), "f"(low))

__device__ __forceinline__ void ldsm_x4(uint32_t* r, uint32_t addr) {
    asm volatile("ldmatrix.sync.aligned.m8n8.x4.shared.b16 {%0,%1,%2,%3}, [%4];"
                 : "=r"(r[0]), "=r"(r[1]), "=r"(r[2]), "=r"(r[3]) : "r"(addr));
}
__device__ __forceinline__ void mma16816(float* c, const uint32_t* a, const uint32_t* b) {
    asm volatile("mma.sync.aligned.m16n8k16.row.col.f32.bf16.bf16.f32 "
                 "{%0,%1,%2,%3}, {%4,%5,%6,%7}, {%8,%9}, {%0,%1,%2,%3};"
                 : "+f"(c[0]), "+f"(c[1]), "+f"(c[2]), "+f"(c[3])
                 : "r"(a[0]), "r"(a[1]), "r"(a[2]), "r"(a[3]), "r"(b[0]), "r"(b[1]));
}

// ---------------- static scratch ----------------
__device__ int   g_deg [NMAX];
__device__ int   g_off [NMAX + 1];
__device__ int   g_cur [NMAX];
__device__ int   g_srcs[EMAX];
__device__ int   g_bsum[256];
__device__ float g_dinv[NMAX];
__device__ float g_Wf  [DIM * 64];
__device__ float g_bf  [64];
__device__ float g_bufA[(size_t)NMAX * DIM];
__device__ float g_bufC[(size_t)NMAX * DIM];

// ---------------- CSR build ----------------
__global__ void zero_deg_kernel(int* __restrict__ deg, int n) {
    int i = blockIdx.x * blockDim.x + threadIdx.x;
    if (i < n) deg[i] = 0;
}
__global__ void hist_kernel(const int* __restrict__ dst, int* __restrict__ deg, int E) {
    int e = blockIdx.x * blockDim.x + threadIdx.x;
    if (e < E) atomicAdd(&deg[dst[e]], 1);
}
__global__ __launch_bounds__(256)
void scan_part_kernel(const int* __restrict__ deg, int* __restrict__ bsum, int n) {
    const int tid = threadIdx.x;
    const int base = blockIdx.x * 1024 + tid * 4;
    int s = 0;
#pragma unroll
    for (int i = 0; i < 4; i++) { int idx = base + i; if (idx < n) s += deg[idx]; }
#pragma unroll
    for (int o = 16; o > 0; o >>= 1) s += __shfl_xor_sync(0xffffffffu, s, o);
    __shared__ int ws[8];
    if ((tid & 31) == 0) ws[tid >> 5] = s;
    __syncthreads();
    if (tid == 0) {
        int t = 0;
#pragma unroll
        for (int i = 0; i < 8; i++) t += ws[i];
        bsum[blockIdx.x] = t;
    }
}
__global__ __launch_bounds__(128)
void scan_block_kernel(int* __restrict__ bsum, int nb) {
    __shared__ int sh[128];
    const int tid = threadIdx.x;
    int v = (tid < nb) ? bsum[tid] : 0;
    sh[tid] = v;
    __syncthreads();
    for (int o = 1; o < 128; o <<= 1) {
        int t = (tid >= o) ? sh[tid - o] : 0;
        __syncthreads();
        sh[tid] += t;
        __syncthreads();
    }
    if (tid < nb) bsum[tid] = sh[tid] - v;
}
__global__ __launch_bounds__(256)
void scan_final_kernel(const int* __restrict__ deg, const int* __restrict__ bsum,
                       int* __restrict__ off, int* __restrict__ cur,
                       float* __restrict__ dinv, int n) {
    const int tid = threadIdx.x;
    const int lane = tid & 31, w = tid >> 5;
    const int base = blockIdx.x * 1024 + tid * 4;
    int d[4]; int s = 0;
#pragma unroll
    for (int i = 0; i < 4; i++) { int idx = base + i; d[i] = (idx < n) ? deg[idx] : 0; s += d[i]; }
    int inc = s;
#pragma unroll
    for (int o = 1; o < 32; o <<= 1) {
        int t = __shfl_up_sync(0xffffffffu, inc, o);
        if (lane >= o) inc += t;
    }
    __shared__ int ws[8];
    if (lane == 31) ws[w] = inc;
    __syncthreads();
    if (w == 0 && lane < 8) {
        int v = ws[lane];
#pragma unroll
        for (int o = 1; o < 8; o <<= 1) {
            int t = __shfl_up_sync(0x000000ffu, v, o);
            if (lane >= o) v += t;
        }
        ws[lane] = v;
    }
    __syncthreads();
    int run = inc - s + (w > 0 ? ws[w - 1] : 0) + bsum[blockIdx.x];
#pragma unroll
    for (int i = 0; i < 4; i++) {
        int idx = base + i;
        if (idx < n) {
            off[idx] = run; cur[idx] = run;
            dinv[idx] = rsqrtf((float)d[i] + 1.0f);
            run += d[i];
            if (idx == n - 1) off[n] = run;
        }
    }
}
__global__ void bucket_kernel(const int* __restrict__ src, const int* __restrict__ dst,
                              int* __restrict__ cur, int* __restrict__ sorted, int E) {
    int e = blockIdx.x * blockDim.x + threadIdx.x;
    if (e < E) { int p = atomicAdd(&cur[dst[e]], 1); sorted[p] = src[e]; }
}

// ---------------- fuse heads: Wf = Wp1 @ Wp2, bf = bp1 @ Wp2 + bp2 ----------------
__global__ void fuse_heads_kernel(const float* __restrict__ Wp1, const float* __restrict__ bp1,
                                  const float* __restrict__ Wp2, const float* __restrict__ bp2,
                                  float* __restrict__ Wf, float* __restrict__ bf) {
    int idx = blockIdx.x * blockDim.x + threadIdx.x;
    if (idx < 128 * 64) {
        int i = idx >> 6, j = idx & 63;
        float s = 0.f;
#pragma unroll 8
        for (int k = 0; k < 128; k++)
            s = fmaf(__ldg(&Wp1[i * 128 + k]), __ldg(&Wp2[k * 64 + j]), s);
        Wf[idx] = s;
    } else if (idx < 128 * 64 + 64) {
        int j = idx - 128 * 64;
        float s = __ldg(&bp2[j]);
#pragma unroll 8
        for (int k = 0; k < 128; k++)
            s = fmaf(__ldg(&bp1[k]), __ldg(&Wp2[k * 64 + j]), s);
        bf[j] = s;
    }
}

// ================= HMMA GEMM: out = A[M,128] @ W[128,BN], fp32 via bf16 3-way split =================
// mma.sync.m16n8k16 (baseline PTX, compiles for compute_103). Persistent, 148 CTAs x 256 thr.
// Tile BM=128 x BN; warp grid 4m x 2n; per warp 2 m16-tiles x NT n8-tiles, 3 split-MMAs each.
// Wt (n-major) hi/lo staged once in smem (272B row stride: conflict-free ldmatrix);
// A converted to bf16 hi/lo smem per tile.
// MODE 0: v *= dinv[row]      MODE 2: v = sigmoid(v + bias[col])
template <int BN, int MODE>
__global__ __launch_bounds__(256)
void mma_gemm_kernel(const float* __restrict__ A, const float* __restrict__ W,
                     const float* __restrict__ bias, const float* __restrict__ dinv,
                     float* __restrict__ out, int M, int ntiles) {
    constexpr int NT = BN / 16;            // n8-tiles per warp (8 or 4)
    constexpr int RS = 272;                // smem row stride bytes (136 bf16 = 17*16B)
    constexpr int WB = BN * RS;            // one W split
    constexpr int AB = 128 * RS;           // one A split
    constexpr int OFF_WHI = 1024;
    constexpr int OFF_WLO = 1024 + WB;
    constexpr int OFF_AHI = 1024 + 2 * WB;
    constexpr int OFF_ALO = 1024 + 2 * WB + AB;

    extern __shared__ char smem[];
    float* sbias = (float*)smem;           // [BN] floats at offset 0
    const uint32_t sb = smem_to_u32(smem);
    const int tid = threadIdx.x;
    const int wid = tid >> 5, lane = tid & 31;
    const int wm = wid >> 1;               // 0..3
    const int wn = wid & 1;                // 0..1

    // ---- stage Wt hi/lo once: Wt[n][k], W input is [k][n] row-major ----
    for (int i = tid; i < BN * 128; i += 256) {
        int nn = i >> 7, k = i & 127;
        float w = __ldg(&W[(size_t)k * BN + nn]);
        __nv_bfloat16 h = __float2bfloat16(w);
        __nv_bfloat16 l = __float2bfloat16(w - __bfloat162float(h));
        *(__nv_bfloat16*)(smem + OFF_WHI + nn * RS + k * 2) = h;
        *(__nv_bfloat16*)(smem + OFF_WLO + nn * RS + k * 2) = l;
    }
    if (MODE == 2 && tid < BN) sbias[tid] = __ldg(&bias[tid]);
    __syncthreads();

    // ldmatrix lane addresses (see fragment mapping of m16n8k16 row.col)
    const int arow = wm * 32 + (lane & 7) + ((lane >> 3) & 1) * 8;
    const int acol = ((lane >> 4) & 1) * 8;               // k offset within k16
    const uint32_t aHi = sb + OFF_AHI + arow * RS + acol * 2;
    const uint32_t aLo = sb + OFF_ALO + arow * RS + acol * 2;
    const int brow = wn * (BN / 2) + (lane & 7) + ((lane >> 4) & 1) * 8;
    const int bcol = ((lane >> 3) & 1) * 8;
    const uint32_t bHi = sb + OFF_WHI + brow * RS + bcol * 2;
    const uint32_t bLo = sb + OFF_WLO + brow * RS + bcol * 2;

    for (int tile = blockIdx.x; tile < ntiles; tile += gridDim.x) {
        const int rowbase = tile * 128;
        __syncthreads();   // previous tile's ldmatrix readers done with sA

        // ---- stage A tile (128x128 fp32 -> bf16 hi/lo smem) ----
#pragma unroll
        for (int it = 0; it < 16; it++) {
            int i = tid + it * 256;
            int r = i >> 5, c4 = i & 31;
            int grow = rowbase + r;
            float4 v = (grow < M) ? ((const float4*)(A + (size_t)grow * 128))[c4]
                                  : make_float4(0.f, 0.f, 0.f, 0.f);
            uint32_t h01, h23, l01, l23;
            CVT_PACK(h01, v.y, v.x);
            float r0 = v.x - __uint_as_float(h01 << 16);
            float r1 = v.y - __uint_as_float(h01 & 0xffff0000u);
            CVT_PACK(l01, r1, r0);
            CVT_PACK(h23, v.w, v.z);
            float r2 = v.z - __uint_as_float(h23 << 16);
            float r3 = v.w - __uint_as_float(h23 & 0xffff0000u);
            CVT_PACK(l23, r3, r2);
            *(uint2*)(smem + OFF_AHI + r * RS + c4 * 8) = make_uint2(h01, h23);
            *(uint2*)(smem + OFF_ALO + r * RS + c4 * 8) = make_uint2(l01, l23);
        }
        __syncthreads();

        // ---- MMA mainloop ----
        float c[2][NT][4];
#pragma unroll
        for (int mt = 0; mt < 2; mt++)
#pragma unroll
            for (int nt = 0; nt < NT; nt++)
#pragma unroll
                for (int j = 0; j < 4; j++) c[mt][nt][j] = 0.f;

#pragma unroll
        for (int ks = 0; ks < 8; ks++) {
            uint32_t ahi[2][4], alo[2][4];
#pragma unroll
            for (int mt = 0; mt < 2; mt++) {
                ldsm_x4(ahi[mt], aHi + mt * (16 * RS) + ks * 32);
                ldsm_x4(alo[mt], aLo + mt * (16 * RS) + ks * 32);
            }
            uint32_t bhi[NT][2], blo[NT][2];
#pragma unroll
            for (int g = 0; g < NT / 2; g++) {
                uint32_t r4[4];
                ldsm_x4(r4, bHi + g * (16 * RS) + ks * 32);
                bhi[2 * g][0] = r4[0]; bhi[2 * g][1] = r4[1];
                bhi[2 * g + 1][0] = r4[2]; bhi[2 * g + 1][1] = r4[3];
                ldsm_x4(r4, bLo + g * (16 * RS) + ks * 32);
                blo[2 * g][0] = r4[0]; blo[2 * g][1] = r4[1];
                blo[2 * g + 1][0] = r4[2]; blo[2 * g + 1][1] = r4[3];
            }
#pragma unroll
            for (int mt = 0; mt < 2; mt++)
#pragma unroll
                for (int nt = 0; nt < NT; nt++) {
                    mma16816(c[mt][nt], ahi[mt], bhi[nt]);
                    mma16816(c[mt][nt], ahi[mt], blo[nt]);
                    mma16816(c[mt][nt], alo[mt], bhi[nt]);
                }
        }

        // ---- epilogue: c frag (row = lane>>2 [+8], col pair = (lane&3)*2) ----
        const int rowt = lane >> 2;
        const int colp = (lane & 3) * 2;
#pragma unroll
        for (int mt = 0; mt < 2; mt++) {
#pragma unroll
            for (int h = 0; h < 2; h++) {
                const int row = rowbase + wm * 32 + mt * 16 + h * 8 + rowt;
                if (row < M) {
                    const float sc = (MODE == 0) ? __ldg(&dinv[row]) : 0.f;
#pragma unroll
                    for (int nt = 0; nt < NT; nt++) {
                        const int nn = wn * (BN / 2) + nt * 8 + colp;
                        float v0 = c[mt][nt][2 * h], v1 = c[mt][nt][2 * h + 1];
                        float2* o = (float2*)(out + (size_t)row * BN + nn);
                        if (MODE == 0) {
                            *o = make_float2(v0 * sc, v1 * sc);
                        } else {
                            float t0 = v0 + sbias[nn], t1 = v1 + sbias[nn + 1];
                            *o = make_float2(1.f / (1.f + __expf(-t0)),
                                             1.f / (1.f + __expf(-t1)));
                        }
                    }
                }
            }
        }
    }
}

// ---------------- fused CSR aggregate + self-loop + dinv + bias + ReLU (+LN) ----------------
template <int DO_LN>
__global__ __launch_bounds__(256)
void aggregate_kernel(const float4* __restrict__ z, const int* __restrict__ off,
                      const int* __restrict__ srcs, const float* __restrict__ dinv,
                      const float* __restrict__ b, const float* __restrict__ g,
                      const float* __restrict__ be, float4* __restrict__ out, int n) {
    const int warp = (blockIdx.x * blockDim.x + threadIdx.x) >> 5;
    const int lane = threadIdx.x & 31;
    if (warp >= n) return;

    const int s0 = __ldg(&off[warp]);
    const int s1 = __ldg(&off[warp + 1]);

    float4 acc = __ldg(&z[(size_t)warp * 32 + lane]);   // self loop
    for (int base = s0; base < s1; base += 32) {
        const int cnt = min(32, s1 - base);
        int mys = (base + lane < s1) ? __ldg(&srcs[base + lane]) : 0;
#pragma unroll 8
        for (int j = 0; j < cnt; j++) {
            int sn = __shfl_sync(0xffffffffu, mys, j);
            float4 v = __ldg(&z[(size_t)sn * 32 + lane]);
            acc.x += v.x; acc.y += v.y; acc.z += v.z; acc.w += v.w;
        }
    }

    const float dv = __ldg(&dinv[warp]);
    const float4 bb = ((const float4*)b)[lane];
    float4 v = make_float4(fmaxf(fmaf(dv, acc.x, bb.x), 0.f),
                           fmaxf(fmaf(dv, acc.y, bb.y), 0.f),
                           fmaxf(fmaf(dv, acc.z, bb.z), 0.f),
                           fmaxf(fmaf(dv, acc.w, bb.w), 0.f));
    if (DO_LN) {
        float s = v.x + v.y + v.z + v.w;
#pragma unroll
        for (int o = 16; o > 0; o >>= 1) s += __shfl_xor_sync(0xffffffffu, s, o);
        const float mu = s * (1.f / 128.f);
        float4 xc = make_float4(v.x - mu, v.y - mu, v.z - mu, v.w - mu);
        float s2 = xc.x * xc.x + xc.y * xc.y + xc.z * xc.z + xc.w * xc.w;
#pragma unroll
        for (int o = 16; o > 0; o >>= 1) s2 += __shfl_xor_sync(0xffffffffu, s2, o);
        const float rs = rsqrtf(s2 * (1.f / 128.f) + LN_EPS);
        const float4 gg = ((const float4*)g)[lane];
        const float4 ee = ((const float4*)be)[lane];
        v = make_float4(fmaf(gg.x * xc.x, rs, ee.x), fmaf(gg.y * xc.y, rs, ee.y),
                        fmaf(gg.z * xc.z, rs, ee.z), fmaf(gg.w * xc.w, rs, ee.w));
    }
    out[(size_t)warp * 32 + lane] = v;
}

// ---------------- launch ----------------
extern "C" void kernel_launch(void* const* d_in, const int* in_sizes, int n_in,
                              void* d_out, int out_size) {
    const float* x   = (const float*)d_in[0];
    const int*   ei  = (const int*)  d_in[1];
    const float* W1  = (const float*)d_in[2];
    const float* b1  = (const float*)d_in[3];
    const float* W2  = (const float*)d_in[4];
    const float* b2  = (const float*)d_in[5];
    const float* W3  = (const float*)d_in[6];
    const float* b3  = (const float*)d_in[7];
    const float* g1  = (const float*)d_in[8];
    const float* be1 = (const float*)d_in[9];
    const float* g2  = (const float*)d_in[10];
    const float* be2 = (const float*)d_in[11];
    const float* Wp1 = (const float*)d_in[12];
    const float* bp1 = (const float*)d_in[13];
    const float* Wp2 = (const float*)d_in[14];
    const float* bp2 = (const float*)d_in[15];
    float* out = (float*)d_out;

    const int n = in_sizes[0] / DIM;          // 100000
    const int E = in_sizes[1] / 2;            // 1600000
    const int* src = ei;
    const int* dst = ei + E;

    int *deg, *off, *cur, *srcs, *bsum;
    float *dinv, *bufA, *bufC, *Wf, *bf;
    cudaGetSymbolAddress((void**)&deg,  g_deg);
    cudaGetSymbolAddress((void**)&off,  g_off);
    cudaGetSymbolAddress((void**)&cur,  g_cur);
    cudaGetSymbolAddress((void**)&srcs, g_srcs);
    cudaGetSymbolAddress((void**)&bsum, g_bsum);
    cudaGetSymbolAddress((void**)&dinv, g_dinv);
    cudaGetSymbolAddress((void**)&bufA, g_bufA);
    cudaGetSymbolAddress((void**)&bufC, g_bufC);
    cudaGetSymbolAddress((void**)&Wf,   g_Wf);
    cudaGetSymbolAddress((void**)&bf,   g_bf);

    // smem: 1024 header + 2 W splits + 2 A splits (272B row stride)
    const int SM128 = 1024 + 2 * (128 * 272) + 2 * (128 * 272);  // 140288
    const int SM64  = 1024 + 2 * (64 * 272)  + 2 * (128 * 272);  // 105472
    cudaFuncSetAttribute(mma_gemm_kernel<128, 0>, cudaFuncAttributeMaxDynamicSharedMemorySize, SM128);
    cudaFuncSetAttribute(mma_gemm_kernel<64,  2>, cudaFuncAttributeMaxDynamicSharedMemorySize, SM64);

    const int ntiles = (n + 127) / 128;              // 782
    const int GEMM_GRID = 148;                       // persistent
    const int agg_grid = (n * 32 + 255) / 256;
    const int nscan = (n + 1023) / 1024;

    // ---- CSR build + fused head weights ----
    zero_deg_kernel<<<(n + 255) / 256, 256>>>(deg, n);
    hist_kernel<<<(E + 255) / 256, 256>>>(dst, deg, E);
    fuse_heads_kernel<<<33, 256>>>(Wp1, bp1, Wp2, bp2, Wf, bf);
    scan_part_kernel <<<nscan, 256>>>(deg, bsum, n);
    scan_block_kernel<<<1, 128>>>(bsum, nscan);
    scan_final_kernel<<<nscan, 256>>>(deg, bsum, off, cur, dinv, n);
    bucket_kernel<<<(E + 255) / 256, 256>>>(src, dst, cur, srcs, E);

    // ---- conv1 ----
    mma_gemm_kernel<128, 0><<<GEMM_GRID, 256, SM128>>>(x, W1, nullptr, dinv, bufA, n, ntiles);
    aggregate_kernel<1><<<agg_grid, 256>>>((const float4*)bufA, off, srcs, dinv, b1, g1, be1, (float4*)bufC, n);

    // ---- conv2 ----
    mma_gemm_kernel<128, 0><<<GEMM_GRID, 256, SM128>>>(bufC, W2, nullptr, dinv, bufA, n, ntiles);
    aggregate_kernel<1><<<agg_grid, 256>>>((const float4*)bufA, off, srcs, dinv, b2, g2, be2, (float4*)bufC, n);

    // ---- conv3 (no LN) ----
    mma_gemm_kernel<128, 0><<<GEMM_GRID, 256, SM128>>>(bufC, W3, nullptr, dinv, bufA, n, ntiles);
    aggregate_kernel<0><<<agg_grid, 256>>>((const float4*)bufA, off, srcs, dinv, b3, nullptr, nullptr, (float4*)bufC, n);

    // ---- fused head: out = sigmoid(h @ Wf + bf) ----
    mma_gemm_kernel<64, 2><<<GEMM_GRID, 256, SM64>>>(bufC, Wf, bf, nullptr, out, n, ntiles);
}

// round 11
// speedup vs baseline: 2.4782x; 1.1064x over previous
#include <cuda_runtime.h>
#include <cuda_bf16.h>
#include <math.h>
#include <stdint.h>

#define NMAX 100000
#define EMAX 2000000
#define DIM 128
#define LN_EPS 1e-5f

// ---------------- helpers ----------------
__device__ __forceinline__ uint32_t smem_to_u32(const void* p) {
    uint32_t a;
    asm("{ .reg .u64 t; cvta.to.shared.u64 t, %1; cvt.u32.u64 %0, t; }" : "=r"(a) : "l"(p));
    return a;
}
// pack two fp32 -> bf16x2 (up -> high 16 bits, low -> low 16 bits)
#define CVT_PACK(res, up, low) \
    asm("cvt.rn.bf16x2.f32 %0, %1, %2;" : "=r"(res) : "f"(up), "f"(low))

__device__ __forceinline__ void ldsm_x4(uint32_t* r, uint32_t addr) {
    asm volatile("ldmatrix.sync.aligned.m8n8.x4.shared.b16 {%0,%1,%2,%3}, [%4];"
                 : "=r"(r[0]), "=r"(r[1]), "=r"(r[2]), "=r"(r[3]) : "r"(addr));
}
__device__ __forceinline__ void mma16816(float* c, const uint32_t* a, const uint32_t* b) {
    asm volatile("mma.sync.aligned.m16n8k16.row.col.f32.bf16.bf16.f32 "
                 "{%0,%1,%2,%3}, {%4,%5,%6,%7}, {%8,%9}, {%0,%1,%2,%3};"
                 : "+f"(c[0]), "+f"(c[1]), "+f"(c[2]), "+f"(c[3])
                 : "r"(a[0]), "r"(a[1]), "r"(a[2]), "r"(a[3]), "r"(b[0]), "r"(b[1]));
}
// exact bf16x2 -> 2x fp32 (bf16 bits are the top 16 of fp32)
__device__ __forceinline__ float4 unpack_bf4(uint2 u) {
    return make_float4(__uint_as_float(u.x << 16), __uint_as_float(u.x & 0xffff0000u),
                       __uint_as_float(u.y << 16), __uint_as_float(u.y & 0xffff0000u));
}

// ---------------- static scratch ----------------
__device__ int      g_deg [NMAX];
__device__ int      g_off [NMAX + 1];
__device__ int      g_cur [NMAX];
__device__ int      g_srcs[EMAX];
__device__ int      g_bsum[256];
__device__ float    g_dinv[NMAX];
__device__ float    g_Wf  [DIM * 64];
__device__ float    g_bf  [64];
__device__ uint32_t g_zb  [(size_t)NMAX * 64];     // z as packed bf16x2 (64 u32 per row)
__device__ float    g_bufC[(size_t)NMAX * DIM];    // layer activations (fp32)

// ---------------- CSR build ----------------
__global__ void zero_deg_kernel(int* __restrict__ deg, int n) {
    int i = blockIdx.x * blockDim.x + threadIdx.x;
    if (i < n) deg[i] = 0;
}
__global__ void hist_kernel(const int* __restrict__ dst, int* __restrict__ deg, int E) {
    int e = blockIdx.x * blockDim.x + threadIdx.x;
    if (e < E) atomicAdd(&deg[dst[e]], 1);
}
__global__ __launch_bounds__(256)
void scan_part_kernel(const int* __restrict__ deg, int* __restrict__ bsum, int n) {
    const int tid = threadIdx.x;
    const int base = blockIdx.x * 1024 + tid * 4;
    int s = 0;
#pragma unroll
    for (int i = 0; i < 4; i++) { int idx = base + i; if (idx < n) s += deg[idx]; }
#pragma unroll
    for (int o = 16; o > 0; o >>= 1) s += __shfl_xor_sync(0xffffffffu, s, o);
    __shared__ int ws[8];
    if ((tid & 31) == 0) ws[tid >> 5] = s;
    __syncthreads();
    if (tid == 0) {
        int t = 0;
#pragma unroll
        for (int i = 0; i < 8; i++) t += ws[i];
        bsum[blockIdx.x] = t;
    }
}
__global__ __launch_bounds__(128)
void scan_block_kernel(int* __restrict__ bsum, int nb) {
    __shared__ int sh[128];
    const int tid = threadIdx.x;
    int v = (tid < nb) ? bsum[tid] : 0;
    sh[tid] = v;
    __syncthreads();
    for (int o = 1; o < 128; o <<= 1) {
        int t = (tid >= o) ? sh[tid - o] : 0;
        __syncthreads();
        sh[tid] += t;
        __syncthreads();
    }
    if (tid < nb) bsum[tid] = sh[tid] - v;
}
__global__ __launch_bounds__(256)
void scan_final_kernel(const int* __restrict__ deg, const int* __restrict__ bsum,
                       int* __restrict__ off, int* __restrict__ cur,
                       float* __restrict__ dinv, int n) {
    const int tid = threadIdx.x;
    const int lane = tid & 31, w = tid >> 5;
    const int base = blockIdx.x * 1024 + tid * 4;
    int d[4]; int s = 0;
#pragma unroll
    for (int i = 0; i < 4; i++) { int idx = base + i; d[i] = (idx < n) ? deg[idx] : 0; s += d[i]; }
    int inc = s;
#pragma unroll
    for (int o = 1; o < 32; o <<= 1) {
        int t = __shfl_up_sync(0xffffffffu, inc, o);
        if (lane >= o) inc += t;
    }
    __shared__ int ws[8];
    if (lane == 31) ws[w] = inc;
    __syncthreads();
    if (w == 0 && lane < 8) {
        int v = ws[lane];
#pragma unroll
        for (int o = 1; o < 8; o <<= 1) {
            int t = __shfl_up_sync(0x000000ffu, v, o);
            if (lane >= o) v += t;
        }
        ws[lane] = v;
    }
    __syncthreads();
    int run = inc - s + (w > 0 ? ws[w - 1] : 0) + bsum[blockIdx.x];
#pragma unroll
    for (int i = 0; i < 4; i++) {
        int idx = base + i;
        if (idx < n) {
            off[idx] = run; cur[idx] = run;
            dinv[idx] = rsqrtf((float)d[i] + 1.0f);
            run += d[i];
            if (idx == n - 1) off[n] = run;
        }
    }
}
__global__ void bucket_kernel(const int* __restrict__ src, const int* __restrict__ dst,
                              int* __restrict__ cur, int* __restrict__ sorted, int E) {
    int e = blockIdx.x * blockDim.x + threadIdx.x;
    if (e < E) { int p = atomicAdd(&cur[dst[e]], 1); sorted[p] = src[e]; }
}

// ---------------- fuse heads: Wf = Wp1 @ Wp2, bf = bp1 @ Wp2 + bp2 ----------------
__global__ void fuse_heads_kernel(const float* __restrict__ Wp1, const float* __restrict__ bp1,
                                  const float* __restrict__ Wp2, const float* __restrict__ bp2,
                                  float* __restrict__ Wf, float* __restrict__ bf) {
    int idx = blockIdx.x * blockDim.x + threadIdx.x;
    if (idx < 128 * 64) {
        int i = idx >> 6, j = idx & 63;
        float s = 0.f;
#pragma unroll 8
        for (int k = 0; k < 128; k++)
            s = fmaf(__ldg(&Wp1[i * 128 + k]), __ldg(&Wp2[k * 64 + j]), s);
        Wf[idx] = s;
    } else if (idx < 128 * 64 + 64) {
        int j = idx - 128 * 64;
        float s = __ldg(&bp2[j]);
#pragma unroll 8
        for (int k = 0; k < 128; k++)
            s = fmaf(__ldg(&bp1[k]), __ldg(&Wp2[k * 64 + j]), s);
        bf[j] = s;
    }
}

// ================= HMMA GEMM: fp32 via bf16 3-way split, mma.sync.m16n8k16 =================
// Persistent, 148 CTAs x 256 thr; BM=128 x BN tile; warp grid 4m x 2n.
// MODE 0: z_bf16[row] = (A@W)[row] * dinv[row]   (packed bf16x2 output)
// MODE 2: out[row] = sigmoid((A@W)[row] + bias)  (fp32 output)
template <int BN, int MODE>
__global__ __launch_bounds__(256)
void mma_gemm_kernel(const float* __restrict__ A, const float* __restrict__ W,
                     const float* __restrict__ bias, const float* __restrict__ dinv,
                     float* __restrict__ out, uint32_t* __restrict__ zb,
                     int M, int ntiles) {
    constexpr int NT = BN / 16;
    constexpr int RS = 272;                // smem row stride bytes (136 bf16 = 17*16B)
    constexpr int WB = BN * RS;
    constexpr int AB = 128 * RS;
    constexpr int OFF_WHI = 1024;
    constexpr int OFF_WLO = 1024 + WB;
    constexpr int OFF_AHI = 1024 + 2 * WB;
    constexpr int OFF_ALO = 1024 + 2 * WB + AB;

    extern __shared__ char smem[];
    float* sbias = (float*)smem;
    const uint32_t sb = smem_to_u32(smem);
    const int tid = threadIdx.x;
    const int wid = tid >> 5, lane = tid & 31;
    const int wm = wid >> 1;
    const int wn = wid & 1;

    // stage Wt hi/lo once (Wt[n][k]; W input is [k][n] row-major)
    for (int i = tid; i < BN * 128; i += 256) {
        int nn = i >> 7, k = i & 127;
        float w = __ldg(&W[(size_t)k * BN + nn]);
        __nv_bfloat16 h = __float2bfloat16(w);
        __nv_bfloat16 l = __float2bfloat16(w - __bfloat162float(h));
        *(__nv_bfloat16*)(smem + OFF_WHI + nn * RS + k * 2) = h;
        *(__nv_bfloat16*)(smem + OFF_WLO + nn * RS + k * 2) = l;
    }
    if (MODE == 2 && tid < BN) sbias[tid] = __ldg(&bias[tid]);
    __syncthreads();

    const int arow = wm * 32 + (lane & 7) + ((lane >> 3) & 1) * 8;
    const int acol = ((lane >> 4) & 1) * 8;
    const uint32_t aHi = sb + OFF_AHI + arow * RS + acol * 2;
    const uint32_t aLo = sb + OFF_ALO + arow * RS + acol * 2;
    const int brow = wn * (BN / 2) + (lane & 7) + ((lane >> 4) & 1) * 8;
    const int bcol = ((lane >> 3) & 1) * 8;
    const uint32_t bHi = sb + OFF_WHI + brow * RS + bcol * 2;
    const uint32_t bLo = sb + OFF_WLO + brow * RS + bcol * 2;

    for (int tile = blockIdx.x; tile < ntiles; tile += gridDim.x) {
        const int rowbase = tile * 128;
        __syncthreads();

        // stage A tile (128x128 fp32 -> bf16 hi/lo smem)
#pragma unroll
        for (int it = 0; it < 16; it++) {
            int i = tid + it * 256;
            int r = i >> 5, c4 = i & 31;
            int grow = rowbase + r;
            float4 v = (grow < M) ? ((const float4*)(A + (size_t)grow * 128))[c4]
                                  : make_float4(0.f, 0.f, 0.f, 0.f);
            uint32_t h01, h23, l01, l23;
            CVT_PACK(h01, v.y, v.x);
            float r0 = v.x - __uint_as_float(h01 << 16);
            float r1 = v.y - __uint_as_float(h01 & 0xffff0000u);
            CVT_PACK(l01, r1, r0);
            CVT_PACK(h23, v.w, v.z);
            float r2 = v.z - __uint_as_float(h23 << 16);
            float r3 = v.w - __uint_as_float(h23 & 0xffff0000u);
            CVT_PACK(l23, r3, r2);
            *(uint2*)(smem + OFF_AHI + r * RS + c4 * 8) = make_uint2(h01, h23);
            *(uint2*)(smem + OFF_ALO + r * RS + c4 * 8) = make_uint2(l01, l23);
        }
        __syncthreads();

        float c[2][NT][4];
#pragma unroll
        for (int mt = 0; mt < 2; mt++)
#pragma unroll
            for (int nt = 0; nt < NT; nt++)
#pragma unroll
                for (int j = 0; j < 4; j++) c[mt][nt][j] = 0.f;

#pragma unroll
        for (int ks = 0; ks < 8; ks++) {
            uint32_t ahi[2][4], alo[2][4];
#pragma unroll
            for (int mt = 0; mt < 2; mt++) {
                ldsm_x4(ahi[mt], aHi + mt * (16 * RS) + ks * 32);
                ldsm_x4(alo[mt], aLo + mt * (16 * RS) + ks * 32);
            }
            uint32_t bhi[NT][2], blo[NT][2];
#pragma unroll
            for (int g = 0; g < NT / 2; g++) {
                uint32_t r4[4];
                ldsm_x4(r4, bHi + g * (16 * RS) + ks * 32);
                bhi[2 * g][0] = r4[0]; bhi[2 * g][1] = r4[1];
                bhi[2 * g + 1][0] = r4[2]; bhi[2 * g + 1][1] = r4[3];
                ldsm_x4(r4, bLo + g * (16 * RS) + ks * 32);
                blo[2 * g][0] = r4[0]; blo[2 * g][1] = r4[1];
                blo[2 * g + 1][0] = r4[2]; blo[2 * g + 1][1] = r4[3];
            }
#pragma unroll
            for (int mt = 0; mt < 2; mt++)
#pragma unroll
                for (int nt = 0; nt < NT; nt++) {
                    mma16816(c[mt][nt], ahi[mt], bhi[nt]);
                    mma16816(c[mt][nt], ahi[mt], blo[nt]);
                    mma16816(c[mt][nt], alo[mt], bhi[nt]);
                }
        }

        const int rowt = lane >> 2;
        const int colp = (lane & 3) * 2;
#pragma unroll
        for (int mt = 0; mt < 2; mt++) {
#pragma unroll
            for (int h = 0; h < 2; h++) {
                const int row = rowbase + wm * 32 + mt * 16 + h * 8 + rowt;
                if (row < M) {
                    const float sc = (MODE == 0) ? __ldg(&dinv[row]) : 0.f;
#pragma unroll
                    for (int nt = 0; nt < NT; nt++) {
                        const int nn = wn * (BN / 2) + nt * 8 + colp;
                        float v0 = c[mt][nt][2 * h], v1 = c[mt][nt][2 * h + 1];
                        if (MODE == 0) {
                            uint32_t p;
                            CVT_PACK(p, v1 * sc, v0 * sc);    // low=col nn, high=col nn+1
                            zb[(size_t)row * 64 + (nn >> 1)] = p;
                        } else {
                            float t0 = v0 + sbias[nn], t1 = v1 + sbias[nn + 1];
                            float2* o = (float2*)(out + (size_t)row * BN + nn);
                            *o = make_float2(1.f / (1.f + __expf(-t0)),
                                             1.f / (1.f + __expf(-t1)));
                        }
                    }
                }
            }
        }
    }
}

// ---------------- fused CSR aggregate (bf16 gather) + self-loop + dinv + bias + ReLU (+LN) --------
// one warp per node; lane owns 4 of 128 features (one uint2 of bf16x2); fp32 accumulation
template <int DO_LN>
__global__ __launch_bounds__(256)
void aggregate_kernel(const uint2* __restrict__ z, const int* __restrict__ off,
                      const int* __restrict__ srcs, const float* __restrict__ dinv,
                      const float* __restrict__ b, const float* __restrict__ g,
                      const float* __restrict__ be, float4* __restrict__ out, int n) {
    const int warp = (blockIdx.x * blockDim.x + threadIdx.x) >> 5;
    const int lane = threadIdx.x & 31;
    if (warp >= n) return;

    const int s0 = __ldg(&off[warp]);
    const int s1 = __ldg(&off[warp + 1]);

    float4 acc = unpack_bf4(__ldg(&z[(size_t)warp * 32 + lane]));   // self loop
    for (int base = s0; base < s1; base += 32) {
        const int cnt = min(32, s1 - base);
        int mys = (base + lane < s1) ? __ldg(&srcs[base + lane]) : 0;
#pragma unroll 8
        for (int j = 0; j < cnt; j++) {
            int sn = __shfl_sync(0xffffffffu, mys, j);
            float4 v = unpack_bf4(__ldg(&z[(size_t)sn * 32 + lane]));
            acc.x += v.x; acc.y += v.y; acc.z += v.z; acc.w += v.w;
        }
    }

    const float dv = __ldg(&dinv[warp]);
    const float4 bb = ((const float4*)b)[lane];
    float4 v = make_float4(fmaxf(fmaf(dv, acc.x, bb.x), 0.f),
                           fmaxf(fmaf(dv, acc.y, bb.y), 0.f),
                           fmaxf(fmaf(dv, acc.z, bb.z), 0.f),
                           fmaxf(fmaf(dv, acc.w, bb.w), 0.f));
    if (DO_LN) {
        float s = v.x + v.y + v.z + v.w;
#pragma unroll
        for (int o = 16; o > 0; o >>= 1) s += __shfl_xor_sync(0xffffffffu, s, o);
        const float mu = s * (1.f / 128.f);
        float4 xc = make_float4(v.x - mu, v.y - mu, v.z - mu, v.w - mu);
        float s2 = xc.x * xc.x + xc.y * xc.y + xc.z * xc.z + xc.w * xc.w;
#pragma unroll
        for (int o = 16; o > 0; o >>= 1) s2 += __shfl_xor_sync(0xffffffffu, s2, o);
        const float rs = rsqrtf(s2 * (1.f / 128.f) + LN_EPS);
        const float4 gg = ((const float4*)g)[lane];
        const float4 ee = ((const float4*)be)[lane];
        v = make_float4(fmaf(gg.x * xc.x, rs, ee.x), fmaf(gg.y * xc.y, rs, ee.y),
                        fmaf(gg.z * xc.z, rs, ee.z), fmaf(gg.w * xc.w, rs, ee.w));
    }
    out[(size_t)warp * 32 + lane] = v;
}

// ---------------- launch ----------------
extern "C" void kernel_launch(void* const* d_in, const int* in_sizes, int n_in,
                              void* d_out, int out_size) {
    const float* x   = (const float*)d_in[0];
    const int*   ei  = (const int*)  d_in[1];
    const float* W1  = (const float*)d_in[2];
    const float* b1  = (const float*)d_in[3];
    const float* W2  = (const float*)d_in[4];
    const float* b2  = (const float*)d_in[5];
    const float* W3  = (const float*)d_in[6];
    const float* b3  = (const float*)d_in[7];
    const float* g1  = (const float*)d_in[8];
    const float* be1 = (const float*)d_in[9];
    const float* g2  = (const float*)d_in[10];
    const float* be2 = (const float*)d_in[11];
    const float* Wp1 = (const float*)d_in[12];
    const float* bp1 = (const float*)d_in[13];
    const float* Wp2 = (const float*)d_in[14];
    const float* bp2 = (const float*)d_in[15];
    float* out = (float*)d_out;

    const int n = in_sizes[0] / DIM;          // 100000
    const int E = in_sizes[1] / 2;            // 1600000
    const int* src = ei;
    const int* dst = ei + E;

    int *deg, *off, *cur, *srcs, *bsum;
    float *dinv, *bufC, *Wf, *bf;
    uint32_t* zb;
    cudaGetSymbolAddress((void**)&deg,  g_deg);
    cudaGetSymbolAddress((void**)&off,  g_off);
    cudaGetSymbolAddress((void**)&cur,  g_cur);
    cudaGetSymbolAddress((void**)&srcs, g_srcs);
    cudaGetSymbolAddress((void**)&bsum, g_bsum);
    cudaGetSymbolAddress((void**)&dinv, g_dinv);
    cudaGetSymbolAddress((void**)&zb,   g_zb);
    cudaGetSymbolAddress((void**)&bufC, g_bufC);
    cudaGetSymbolAddress((void**)&Wf,   g_Wf);
    cudaGetSymbolAddress((void**)&bf,   g_bf);

    const int SM128 = 1024 + 2 * (128 * 272) + 2 * (128 * 272);  // 140288
    const int SM64  = 1024 + 2 * (64 * 272)  + 2 * (128 * 272);  // 105472
    cudaFuncSetAttribute(mma_gemm_kernel<128, 0>, cudaFuncAttributeMaxDynamicSharedMemorySize, SM128);
    cudaFuncSetAttribute(mma_gemm_kernel<64,  2>, cudaFuncAttributeMaxDynamicSharedMemorySize, SM64);

    const int ntiles = (n + 127) / 128;              // 782
    const int GEMM_GRID = 148;
    const int agg_grid = (n * 32 + 255) / 256;
    const int nscan = (n + 1023) / 1024;

    // ---- CSR build + fused head weights ----
    zero_deg_kernel<<<(n + 255) / 256, 256>>>(deg, n);
    hist_kernel<<<(E + 255) / 256, 256>>>(dst, deg, E);
    fuse_heads_kernel<<<33, 256>>>(Wp1, bp1, Wp2, bp2, Wf, bf);
    scan_part_kernel <<<nscan, 256>>>(deg, bsum, n);
    scan_block_kernel<<<1, 128>>>(bsum, nscan);
    scan_final_kernel<<<nscan, 256>>>(deg, bsum, off, cur, dinv, n);
    bucket_kernel<<<(E + 255) / 256, 256>>>(src, dst, cur, srcs, E);

    // ---- conv1 ----
    mma_gemm_kernel<128, 0><<<GEMM_GRID, 256, SM128>>>(x, W1, nullptr, dinv, nullptr, zb, n, ntiles);
    aggregate_kernel<1><<<agg_grid, 256>>>((const uint2*)zb, off, srcs, dinv, b1, g1, be1, (float4*)bufC, n);

    // ---- conv2 ----
    mma_gemm_kernel<128, 0><<<GEMM_GRID, 256, SM128>>>(bufC, W2, nullptr, dinv, nullptr, zb, n, ntiles);
    aggregate_kernel<1><<<agg_grid, 256>>>((const uint2*)zb, off, srcs, dinv, b2, g2, be2, (float4*)bufC, n);

    // ---- conv3 (no LN) ----
    mma_gemm_kernel<128, 0><<<GEMM_GRID, 256, SM128>>>(bufC, W3, nullptr, dinv, nullptr, zb, n, ntiles);
    aggregate_kernel<0><<<agg_grid, 256>>>((const uint2*)zb, off, srcs, dinv, b3, nullptr, nullptr, (float4*)bufC, n);

    // ---- fused head: out = sigmoid(h @ Wf + bf) ----
    mma_gemm_kernel<64, 2><<<GEMM_GRID, 256, SM64>>>(bufC, Wf, bf, nullptr, out, nullptr, n, ntiles);
}

// round 12
// speedup vs baseline: 2.7071x; 1.0923x over previous
#include <cuda_runtime.h>
#include <cuda_bf16.h>
#include <math.h>
#include <stdint.h>

#define NMAX 100000
#define EMAX 2000000
#define DIM 128
#define LN_EPS 1e-5f

// ---------------- helpers ----------------
__device__ __forceinline__ uint32_t smem_to_u32(const void* p) {
    uint32_t a;
    asm("{ .reg .u64 t; cvta.to.shared.u64 t, %1; cvt.u32.u64 %0, t; }" : "=r"(a) : "l"(p));
    return a;
}
// pack two fp32 -> bf16x2 (up -> high 16 bits, low -> low 16 bits)
#define CVT_PACK(res, up, low) \
    asm("cvt.rn.bf16x2.f32 %0, %1, %2;" : "=r"(res) : "f"(up), "f"(low))

__device__ __forceinline__ void ldsm_x4(uint32_t* r, uint32_t addr) {
    asm volatile("ldmatrix.sync.aligned.m8n8.x4.shared.b16 {%0,%1,%2,%3}, [%4];"
                 : "=r"(r[0]), "=r"(r[1]), "=r"(r[2]), "=r"(r[3]) : "r"(addr));
}
__device__ __forceinline__ void mma16816(float* c, const uint32_t* a, const uint32_t* b) {
    asm volatile("mma.sync.aligned.m16n8k16.row.col.f32.bf16.bf16.f32 "
                 "{%0,%1,%2,%3}, {%4,%5,%6,%7}, {%8,%9}, {%0,%1,%2,%3};"
                 : "+f"(c[0]), "+f"(c[1]), "+f"(c[2]), "+f"(c[3])
                 : "r"(a[0]), "r"(a[1]), "r"(a[2]), "r"(a[3]), "r"(b[0]), "r"(b[1]));
}
// exact bf16x2 -> 2x fp32 (bf16 bits are the top 16 of fp32; low half = lower index)
__device__ __forceinline__ float4 unpack_bf4(uint2 u) {
    return make_float4(__uint_as_float(u.x << 16), __uint_as_float(u.x & 0xffff0000u),
                       __uint_as_float(u.y << 16), __uint_as_float(u.y & 0xffff0000u));
}

// ---------------- static scratch ----------------
__device__ int      g_deg [NMAX];
__device__ int      g_off [NMAX + 1];
__device__ int      g_cur [NMAX];
__device__ int      g_srcs[EMAX];
__device__ int      g_bsum[256];
__device__ float    g_dinv[NMAX];
__device__ float    g_Wf  [DIM * 64];
__device__ float    g_bf  [64];
__device__ uint32_t g_zb  [(size_t)NMAX * 64];   // z  (GEMM out) packed bf16x2
__device__ uint32_t g_hb  [(size_t)NMAX * 64];   // h  (activations) packed bf16x2

// ---------------- CSR build ----------------
__global__ void zero_deg_kernel(int* __restrict__ deg, int n) {
    int i = blockIdx.x * blockDim.x + threadIdx.x;
    if (i < n) deg[i] = 0;
}
__global__ void hist_kernel(const int* __restrict__ dst, int* __restrict__ deg, int E) {
    int e = blockIdx.x * blockDim.x + threadIdx.x;
    if (e < E) atomicAdd(&deg[dst[e]], 1);
}
__global__ __launch_bounds__(256)
void scan_part_kernel(const int* __restrict__ deg, int* __restrict__ bsum, int n) {
    const int tid = threadIdx.x;
    const int base = blockIdx.x * 1024 + tid * 4;
    int s = 0;
#pragma unroll
    for (int i = 0; i < 4; i++) { int idx = base + i; if (idx < n) s += deg[idx]; }
#pragma unroll
    for (int o = 16; o > 0; o >>= 1) s += __shfl_xor_sync(0xffffffffu, s, o);
    __shared__ int ws[8];
    if ((tid & 31) == 0) ws[tid >> 5] = s;
    __syncthreads();
    if (tid == 0) {
        int t = 0;
#pragma unroll
        for (int i = 0; i < 8; i++) t += ws[i];
        bsum[blockIdx.x] = t;
    }
}
__global__ __launch_bounds__(128)
void scan_block_kernel(int* __restrict__ bsum, int nb) {
    __shared__ int sh[128];
    const int tid = threadIdx.x;
    int v = (tid < nb) ? bsum[tid] : 0;
    sh[tid] = v;
    __syncthreads();
    for (int o = 1; o < 128; o <<= 1) {
        int t = (tid >= o) ? sh[tid - o] : 0;
        __syncthreads();
        sh[tid] += t;
        __syncthreads();
    }
    if (tid < nb) bsum[tid] = sh[tid] - v;
}
__global__ __launch_bounds__(256)
void scan_final_kernel(const int* __restrict__ deg, const int* __restrict__ bsum,
                       int* __restrict__ off, int* __restrict__ cur,
                       float* __restrict__ dinv, int n) {
    const int tid = threadIdx.x;
    const int lane = tid & 31, w = tid >> 5;
    const int base = blockIdx.x * 1024 + tid * 4;
    int d[4]; int s = 0;
#pragma unroll
    for (int i = 0; i < 4; i++) { int idx = base + i; d[i] = (idx < n) ? deg[idx] : 0; s += d[i]; }
    int inc = s;
#pragma unroll
    for (int o = 1; o < 32; o <<= 1) {
        int t = __shfl_up_sync(0xffffffffu, inc, o);
        if (lane >= o) inc += t;
    }
    __shared__ int ws[8];
    if (lane == 31) ws[w] = inc;
    __syncthreads();
    if (w == 0 && lane < 8) {
        int v = ws[lane];
#pragma unroll
        for (int o = 1; o < 8; o <<= 1) {
            int t = __shfl_up_sync(0x000000ffu, v, o);
            if (lane >= o) v += t;
        }
        ws[lane] = v;
    }
    __syncthreads();
    int run = inc - s + (w > 0 ? ws[w - 1] : 0) + bsum[blockIdx.x];
#pragma unroll
    for (int i = 0; i < 4; i++) {
        int idx = base + i;
        if (idx < n) {
            off[idx] = run; cur[idx] = run;
            dinv[idx] = rsqrtf((float)d[i] + 1.0f);
            run += d[i];
            if (idx == n - 1) off[n] = run;
        }
    }
}
__global__ void bucket_kernel(const int* __restrict__ src, const int* __restrict__ dst,
                              int* __restrict__ cur, int* __restrict__ sorted, int E) {
    int e = blockIdx.x * blockDim.x + threadIdx.x;
    if (e < E) { int p = atomicAdd(&cur[dst[e]], 1); sorted[p] = src[e]; }
}

// ---------------- fuse heads: Wf = Wp1 @ Wp2, bf = bp1 @ Wp2 + bp2 ----------------
__global__ void fuse_heads_kernel(const float* __restrict__ Wp1, const float* __restrict__ bp1,
                                  const float* __restrict__ Wp2, const float* __restrict__ bp2,
                                  float* __restrict__ Wf, float* __restrict__ bf) {
    int idx = blockIdx.x * blockDim.x + threadIdx.x;
    if (idx < 128 * 64) {
        int i = idx >> 6, j = idx & 63;
        float s = 0.f;
#pragma unroll 8
        for (int k = 0; k < 128; k++)
            s = fmaf(__ldg(&Wp1[i * 128 + k]), __ldg(&Wp2[k * 64 + j]), s);
        Wf[idx] = s;
    } else if (idx < 128 * 64 + 64) {
        int j = idx - 128 * 64;
        float s = __ldg(&bp2[j]);
#pragma unroll 8
        for (int k = 0; k < 128; k++)
            s = fmaf(__ldg(&bp1[k]), __ldg(&Wp2[k * 64 + j]), s);
        bf[j] = s;
    }
}

// ================= HMMA GEMM (mma.sync.m16n8k16), W always split bf16 hi/lo =================
// ABF16=false: A fp32, 3-term split (hh + h*wlo + alo*whi)  -- conv1 (pristine input)
// ABF16=true : A already packed bf16 rows, 2 MMAs (a*whi + a*wlo) -- convs 2/3, head
// MODE 0: zb[row] = (A@W)[row] * dinv[row]  (packed bf16x2)
// MODE 2: out[row] = sigmoid((A@W)[row] + bias)  (fp32)
template <int BN, int MODE, bool ABF16>
__global__ __launch_bounds__(256)
void mma_gemm_kernel(const void* __restrict__ Ain, const float* __restrict__ W,
                     const float* __restrict__ bias, const float* __restrict__ dinv,
                     float* __restrict__ out, uint32_t* __restrict__ zb,
                     int M, int ntiles) {
    constexpr int NT = BN / 16;
    constexpr int RS = 272;                // smem row stride bytes (136 bf16 = 17*16B)
    constexpr int WB = BN * RS;
    constexpr int OFF_WHI = 1024;
    constexpr int OFF_WLO = 1024 + WB;
    constexpr int OFF_AHI = 1024 + 2 * WB;
    constexpr int OFF_ALO = OFF_AHI + 128 * RS;   // only used when !ABF16

    extern __shared__ char smem[];
    float* sbias = (float*)smem;
    const uint32_t sb = smem_to_u32(smem);
    const int tid = threadIdx.x;
    const int wid = tid >> 5, lane = tid & 31;
    const int wm = wid >> 1;
    const int wn = wid & 1;

    // stage Wt hi/lo once (Wt[n][k]; W input is [k][n] row-major, fp32)
    for (int i = tid; i < BN * 128; i += 256) {
        int nn = i >> 7, k = i & 127;
        float w = __ldg(&W[(size_t)k * BN + nn]);
        __nv_bfloat16 h = __float2bfloat16(w);
        __nv_bfloat16 l = __float2bfloat16(w - __bfloat162float(h));
        *(__nv_bfloat16*)(smem + OFF_WHI + nn * RS + k * 2) = h;
        *(__nv_bfloat16*)(smem + OFF_WLO + nn * RS + k * 2) = l;
    }
    if (MODE == 2 && tid < BN) sbias[tid] = __ldg(&bias[tid]);
    __syncthreads();

    const int arow = wm * 32 + (lane & 7) + ((lane >> 3) & 1) * 8;
    const int acol = ((lane >> 4) & 1) * 8;
    const uint32_t aHi = sb + OFF_AHI + arow * RS + acol * 2;
    const uint32_t aLo = sb + OFF_ALO + arow * RS + acol * 2;
    const int brow = wn * (BN / 2) + (lane & 7) + ((lane >> 4) & 1) * 8;
    const int bcol = ((lane >> 3) & 1) * 8;
    const uint32_t bHi = sb + OFF_WHI + brow * RS + bcol * 2;
    const uint32_t bLo = sb + OFF_WLO + brow * RS + bcol * 2;

    for (int tile = blockIdx.x; tile < ntiles; tile += gridDim.x) {
        const int rowbase = tile * 128;
        __syncthreads();

        if (ABF16) {
            // A already bf16: copy 128 rows x 256B into sAhi (16B chunks)
            const uint4* Ab = (const uint4*)Ain;
#pragma unroll
            for (int it = 0; it < 8; it++) {
                int i = tid + it * 256;
                int r = i >> 4, c = i & 15;
                int grow = rowbase + r;
                uint4 v = (grow < M) ? __ldg(&Ab[(size_t)grow * 16 + c])
                                     : make_uint4(0u, 0u, 0u, 0u);
                *(uint4*)(smem + OFF_AHI + r * RS + c * 16) = v;
            }
        } else {
            // A fp32: convert to bf16 hi/lo smem
            const float* A = (const float*)Ain;
#pragma unroll
            for (int it = 0; it < 16; it++) {
                int i = tid + it * 256;
                int r = i >> 5, c4 = i & 31;
                int grow = rowbase + r;
                float4 v = (grow < M) ? ((const float4*)(A + (size_t)grow * 128))[c4]
                                      : make_float4(0.f, 0.f, 0.f, 0.f);
                uint32_t h01, h23, l01, l23;
                CVT_PACK(h01, v.y, v.x);
                float r0 = v.x - __uint_as_float(h01 << 16);
                float r1 = v.y - __uint_as_float(h01 & 0xffff0000u);
                CVT_PACK(l01, r1, r0);
                CVT_PACK(h23, v.w, v.z);
                float r2 = v.z - __uint_as_float(h23 << 16);
                float r3 = v.w - __uint_as_float(h23 & 0xffff0000u);
                CVT_PACK(l23, r3, r2);
                *(uint2*)(smem + OFF_AHI + r * RS + c4 * 8) = make_uint2(h01, h23);
                *(uint2*)(smem + OFF_ALO + r * RS + c4 * 8) = make_uint2(l01, l23);
            }
        }
        __syncthreads();

        float c[2][NT][4];
#pragma unroll
        for (int mt = 0; mt < 2; mt++)
#pragma unroll
            for (int nt = 0; nt < NT; nt++)
#pragma unroll
                for (int j = 0; j < 4; j++) c[mt][nt][j] = 0.f;

#pragma unroll
        for (int ks = 0; ks < 8; ks++) {
            uint32_t ahi[2][4], alo[2][4];
#pragma unroll
            for (int mt = 0; mt < 2; mt++) {
                ldsm_x4(ahi[mt], aHi + mt * (16 * RS) + ks * 32);
                if (!ABF16) ldsm_x4(alo[mt], aLo + mt * (16 * RS) + ks * 32);
            }
            uint32_t bhi[NT][2], blo[NT][2];
#pragma unroll
            for (int g = 0; g < NT / 2; g++) {
                uint32_t r4[4];
                ldsm_x4(r4, bHi + g * (16 * RS) + ks * 32);
                bhi[2 * g][0] = r4[0]; bhi[2 * g][1] = r4[1];
                bhi[2 * g + 1][0] = r4[2]; bhi[2 * g + 1][1] = r4[3];
                ldsm_x4(r4, bLo + g * (16 * RS) + ks * 32);
                blo[2 * g][0] = r4[0]; blo[2 * g][1] = r4[1];
                blo[2 * g + 1][0] = r4[2]; blo[2 * g + 1][1] = r4[3];
            }
#pragma unroll
            for (int mt = 0; mt < 2; mt++)
#pragma unroll
                for (int nt = 0; nt < NT; nt++) {
                    mma16816(c[mt][nt], ahi[mt], bhi[nt]);
                    mma16816(c[mt][nt], ahi[mt], blo[nt]);
                    if (!ABF16) mma16816(c[mt][nt], alo[mt], bhi[nt]);
                }
        }

        const int rowt = lane >> 2;
        const int colp = (lane & 3) * 2;
#pragma unroll
        for (int mt = 0; mt < 2; mt++) {
#pragma unroll
            for (int h = 0; h < 2; h++) {
                const int row = rowbase + wm * 32 + mt * 16 + h * 8 + rowt;
                if (row < M) {
                    const float sc = (MODE == 0) ? __ldg(&dinv[row]) : 0.f;
#pragma unroll
                    for (int nt = 0; nt < NT; nt++) {
                        const int nn = wn * (BN / 2) + nt * 8 + colp;
                        float v0 = c[mt][nt][2 * h], v1 = c[mt][nt][2 * h + 1];
                        if (MODE == 0) {
                            uint32_t p;
                            CVT_PACK(p, v1 * sc, v0 * sc);
                            zb[(size_t)row * 64 + (nn >> 1)] = p;
                        } else {
                            float t0 = v0 + sbias[nn], t1 = v1 + sbias[nn + 1];
                            float2* o = (float2*)(out + (size_t)row * BN + nn);
                            *o = make_float2(1.f / (1.f + __expf(-t0)),
                                             1.f / (1.f + __expf(-t1)));
                        }
                    }
                }
            }
        }
    }
}

// -------- fused CSR aggregate (bf16 gather, fp32 accum) + self-loop + dinv + bias + ReLU (+LN),
//          bf16 packed output --------
template <int DO_LN>
__global__ __launch_bounds__(256)
void aggregate_kernel(const uint2* __restrict__ z, const int* __restrict__ off,
                      const int* __restrict__ srcs, const float* __restrict__ dinv,
                      const float* __restrict__ b, const float* __restrict__ g,
                      const float* __restrict__ be, uint2* __restrict__ out, int n) {
    const int warp = (blockIdx.x * blockDim.x + threadIdx.x) >> 5;
    const int lane = threadIdx.x & 31;
    if (warp >= n) return;

    const int s0 = __ldg(&off[warp]);
    const int s1 = __ldg(&off[warp + 1]);

    float4 acc = unpack_bf4(__ldg(&z[(size_t)warp * 32 + lane]));   // self loop
    for (int base = s0; base < s1; base += 32) {
        const int cnt = min(32, s1 - base);
        int mys = (base + lane < s1) ? __ldg(&srcs[base + lane]) : 0;
#pragma unroll 8
        for (int j = 0; j < cnt; j++) {
            int sn = __shfl_sync(0xffffffffu, mys, j);
            float4 v = unpack_bf4(__ldg(&z[(size_t)sn * 32 + lane]));
            acc.x += v.x; acc.y += v.y; acc.z += v.z; acc.w += v.w;
        }
    }

    const float dv = __ldg(&dinv[warp]);
    const float4 bb = ((const float4*)b)[lane];
    float4 v = make_float4(fmaxf(fmaf(dv, acc.x, bb.x), 0.f),
                           fmaxf(fmaf(dv, acc.y, bb.y), 0.f),
                           fmaxf(fmaf(dv, acc.z, bb.z), 0.f),
                           fmaxf(fmaf(dv, acc.w, bb.w), 0.f));
    if (DO_LN) {
        float s = v.x + v.y + v.z + v.w;
#pragma unroll
        for (int o = 16; o > 0; o >>= 1) s += __shfl_xor_sync(0xffffffffu, s, o);
        const float mu = s * (1.f / 128.f);
        float4 xc = make_float4(v.x - mu, v.y - mu, v.z - mu, v.w - mu);
        float s2 = xc.x * xc.x + xc.y * xc.y + xc.z * xc.z + xc.w * xc.w;
#pragma unroll
        for (int o = 16; o > 0; o >>= 1) s2 += __shfl_xor_sync(0xffffffffu, s2, o);
        const float rs = rsqrtf(s2 * (1.f / 128.f) + LN_EPS);
        const float4 gg = ((const float4*)g)[lane];
        const float4 ee = ((const float4*)be)[lane];
        v = make_float4(fmaf(gg.x * xc.x, rs, ee.x), fmaf(gg.y * xc.y, rs, ee.y),
                        fmaf(gg.z * xc.z, rs, ee.z), fmaf(gg.w * xc.w, rs, ee.w));
    }
    uint2 p;
    CVT_PACK(p.x, v.y, v.x);
    CVT_PACK(p.y, v.w, v.z);
    out[(size_t)warp * 32 + lane] = p;
}

// ---------------- launch ----------------
extern "C" void kernel_launch(void* const* d_in, const int* in_sizes, int n_in,
                              void* d_out, int out_size) {
    const float* x   = (const float*)d_in[0];
    const int*   ei  = (const int*)  d_in[1];
    const float* W1  = (const float*)d_in[2];
    const float* b1  = (const float*)d_in[3];
    const float* W2  = (const float*)d_in[4];
    const float* b2  = (const float*)d_in[5];
    const float* W3  = (const float*)d_in[6];
    const float* b3  = (const float*)d_in[7];
    const float* g1  = (const float*)d_in[8];
    const float* be1 = (const float*)d_in[9];
    const float* g2  = (const float*)d_in[10];
    const float* be2 = (const float*)d_in[11];
    const float* Wp1 = (const float*)d_in[12];
    const float* bp1 = (const float*)d_in[13];
    const float* Wp2 = (const float*)d_in[14];
    const float* bp2 = (const float*)d_in[15];
    float* out = (float*)d_out;

    const int n = in_sizes[0] / DIM;          // 100000
    const int E = in_sizes[1] / 2;            // 1600000
    const int* src = ei;
    const int* dst = ei + E;

    int *deg, *off, *cur, *srcs, *bsum;
    float *dinv, *Wf, *bf;
    uint32_t *zb, *hb;
    cudaGetSymbolAddress((void**)&deg,  g_deg);
    cudaGetSymbolAddress((void**)&off,  g_off);
    cudaGetSymbolAddress((void**)&cur,  g_cur);
    cudaGetSymbolAddress((void**)&srcs, g_srcs);
    cudaGetSymbolAddress((void**)&bsum, g_bsum);
    cudaGetSymbolAddress((void**)&dinv, g_dinv);
    cudaGetSymbolAddress((void**)&zb,   g_zb);
    cudaGetSymbolAddress((void**)&hb,   g_hb);
    cudaGetSymbolAddress((void**)&Wf,   g_Wf);
    cudaGetSymbolAddress((void**)&bf,   g_bf);

    // smem sizes: header 1024 + 2 W splits + A (1 or 2 splits), RS=272
    const int SM128_FP = 1024 + 2 * (128 * 272) + 2 * (128 * 272);  // 140288 (conv1)
    const int SM128_BF = 1024 + 2 * (128 * 272) + 1 * (128 * 272);  // 105472 (convs 2/3)
    const int SM64_BF  = 1024 + 2 * (64 * 272)  + 1 * (128 * 272);  //  70656 (head)
    cudaFuncSetAttribute(mma_gemm_kernel<128, 0, false>, cudaFuncAttributeMaxDynamicSharedMemorySize, SM128_FP);
    cudaFuncSetAttribute(mma_gemm_kernel<128, 0, true>,  cudaFuncAttributeMaxDynamicSharedMemorySize, SM128_BF);
    cudaFuncSetAttribute(mma_gemm_kernel<64,  2, true>,  cudaFuncAttributeMaxDynamicSharedMemorySize, SM64_BF);

    const int ntiles = (n + 127) / 128;              // 782
    const int GEMM_GRID = 148;                       // persistent (2 CTAs/SM where smem allows -> 296)
    const int GEMM_GRID2 = 296;
    const int agg_grid = (n * 32 + 255) / 256;
    const int nscan = (n + 1023) / 1024;

    // ---- CSR build + fused head weights ----
    zero_deg_kernel<<<(n + 255) / 256, 256>>>(deg, n);
    hist_kernel<<<(E + 255) / 256, 256>>>(dst, deg, E);
    fuse_heads_kernel<<<33, 256>>>(Wp1, bp1, Wp2, bp2, Wf, bf);
    scan_part_kernel <<<nscan, 256>>>(deg, bsum, n);
    scan_block_kernel<<<1, 128>>>(bsum, nscan);
    scan_final_kernel<<<nscan, 256>>>(deg, bsum, off, cur, dinv, n);
    bucket_kernel<<<(E + 255) / 256, 256>>>(src, dst, cur, srcs, E);

    // ---- conv1 (fp32 A, 3-term split) ----
    mma_gemm_kernel<128, 0, false><<<GEMM_GRID, 256, SM128_FP>>>(x, W1, nullptr, dinv, nullptr, zb, n, ntiles);
    aggregate_kernel<1><<<agg_grid, 256>>>((const uint2*)zb, off, srcs, dinv, b1, g1, be1, (uint2*)hb, n);

    // ---- conv2 (bf16 A) ----
    mma_gemm_kernel<128, 0, true><<<GEMM_GRID2, 256, SM128_BF>>>(hb, W2, nullptr, dinv, nullptr, zb, n, ntiles);
    aggregate_kernel<1><<<agg_grid, 256>>>((const uint2*)zb, off, srcs, dinv, b2, g2, be2, (uint2*)hb, n);

    // ---- conv3 (bf16 A, no LN) ----
    mma_gemm_kernel<128, 0, true><<<GEMM_GRID2, 256, SM128_BF>>>(hb, W3, nullptr, dinv, nullptr, zb, n, ntiles);
    aggregate_kernel<0><<<agg_grid, 256>>>((const uint2*)zb, off, srcs, dinv, b3, nullptr, nullptr, (uint2*)hb, n);

    // ---- fused head: out = sigmoid(h @ Wf + bf) (bf16 A) ----
    mma_gemm_kernel<64, 2, true><<<GEMM_GRID2, 256, SM64_BF>>>(hb, Wf, bf, nullptr, out, nullptr, n, ntiles);
}